// round 3
// baseline (speedup 1.0000x reference)
#include <cuda_runtime.h>

#define NN 200000
#define EE 400000
#define DD 64
#define BBATCH 16
#define NLVL 12
#define SCAN_NB ((NN + 1023) / 1024)   // 196
#define PGRID 296                      // persistent grid: 148 SMs x occupancy 2

// ---------------- device scratch (no allocations allowed) ----------------
__device__ float g_h[NN * DD];          // node states
__device__ float g_agg[NN * DD];        // per-level gathered sums (indexed by node id)
__device__ int g_indeg[NN], g_outdeg[NN];
__device__ int g_in_ptr[NN + 1], g_out_ptr[NN + 1];
__device__ int g_cur_in[NN], g_cur_out[NN];
__device__ int g_csr_src[EE];           // in-edges grouped by dst
__device__ int g_csc_dst[EE];           // out-edges grouped by src
__device__ int g_fnodes[NN], g_bnodes[NN];
__device__ int g_fhist[NLVL], g_bhist[NLVL];
__device__ int g_foff[NLVL + 1], g_boff[NLVL + 1];
__device__ int g_fcur[NLVL], g_bcur[NLVL];
__device__ int g_bsum[2][SCAN_NB], g_bsum_s[2][SCAN_NB];

// grid barrier state (generation counter survives across graph replays)
__device__ unsigned g_cnt = 0;
__device__ volatile unsigned g_gen = 0;

// ordered-uint encoding for atomic float max
__device__ __forceinline__ unsigned enc_f(float f) {
    unsigned u = __float_as_uint(f);
    return (u & 0x80000000u) ? ~u : (u | 0x80000000u);
}
__device__ __forceinline__ float dec_f(unsigned u) {
    return (u & 0x80000000u) ? __uint_as_float(u & 0x7FFFFFFFu)
                             : __uint_as_float(~u);
}

#define NEGMAX (-3.402823466e38f)

// ---------------- K1: init h (float4), zero counters, init output ----------------
__global__ void k_init(const int* __restrict__ nt, const int* __restrict__ nip,
                       const float* __restrict__ Wenc, const float* __restrict__ benc,
                       float* __restrict__ out) {
    int stride = gridDim.x * blockDim.x;
    // NN*DD/4 = 3.2M float4 elements
    for (int q = blockIdx.x * blockDim.x + threadIdx.x; q < NN * DD / 4; q += stride) {
        int n = q >> 4;              // 16 float4 per node
        int d = (q & 15) << 2;       // starting dim
        float a = (float)nt[n], b = (float)nip[n];
        float4 w0 = *(const float4*)(Wenc + d);
        float4 w1 = *(const float4*)(Wenc + 64 + d);
        float4 be = *(const float4*)(benc + d);
        float4 o;
        o.x = a * w0.x + b * w1.x + be.x;
        o.y = a * w0.y + b * w1.y + be.y;
        o.z = a * w0.z + b * w1.z + be.z;
        o.w = a * w0.w + b * w1.w + be.w;
        *(float4*)(g_h + (size_t)q * 4) = o;
        if (q < NN) { g_indeg[q] = 0; g_outdeg[q] = 0; }
        if (q < NLVL) { g_fhist[q] = 0; g_bhist[q] = 0; }
        if (q < BBATCH * 2 * DD) {
            int col = q & 127;
            ((unsigned*)out)[q] = (col < 64) ? 0x00800000u : 0u;
        }
    }
}

// ---------------- K2: degrees + level histograms ----------------
__global__ void k_deg(const int* __restrict__ ei, const int* __restrict__ fl,
                      const int* __restrict__ bl) {
    int stride = gridDim.x * blockDim.x;
    for (int i = blockIdx.x * blockDim.x + threadIdx.x; i < EE; i += stride) {
        atomicAdd(&g_indeg[ei[EE + i]], 1);   // dst
        atomicAdd(&g_outdeg[ei[i]], 1);       // src
        if (i < NN) {
            atomicAdd(&g_fhist[fl[i]], 1);
            atomicAdd(&g_bhist[bl[i]], 1);
        }
    }
}

// ---------------- K3: block-local exclusive scans of indeg/outdeg ----------------
__global__ void k_scan1() {
    int which = blockIdx.x / SCAN_NB;   // 0 = indeg, 1 = outdeg
    int blk = blockIdx.x % SCAN_NB;
    const int* deg = which ? g_outdeg : g_indeg;
    int* ptr = which ? g_out_ptr : g_in_ptr;
    __shared__ int sh[256];
    int base = blk * 1024 + threadIdx.x * 4;
    int v[4];
    int s = 0;
#pragma unroll
    for (int j = 0; j < 4; j++) {
        int idx = base + j;
        v[j] = (idx < NN) ? deg[idx] : 0;
        s += v[j];
    }
    sh[threadIdx.x] = s;
    __syncthreads();
    for (int off = 1; off < 256; off <<= 1) {
        int t = 0;
        if (threadIdx.x >= off) t = sh[threadIdx.x - off];
        __syncthreads();
        sh[threadIdx.x] += t;
        __syncthreads();
    }
    int run = sh[threadIdx.x] - s;   // exclusive prefix within block
#pragma unroll
    for (int j = 0; j < 4; j++) {
        int idx = base + j;
        if (idx < NN) ptr[idx] = run;
        run += v[j];
    }
    if (threadIdx.x == 255) g_bsum[which][blk] = sh[255];
}

// ---------------- K4: PARALLEL scan of block sums + level hists ----------------
__global__ void k_scan2p() {
    __shared__ int sh[256];
    int t = threadIdx.x;
#pragma unroll
    for (int w = 0; w < 2; w++) {
        int v = (t < SCAN_NB) ? g_bsum[w][t] : 0;
        sh[t] = v;
        __syncthreads();
        for (int off = 1; off < 256; off <<= 1) {
            int x = 0;
            if (t >= off) x = sh[t - off];
            __syncthreads();
            sh[t] += x;
            __syncthreads();
        }
        if (t < SCAN_NB) g_bsum_s[w][t] = sh[t] - v;
        __syncthreads();
    }
    // warp 0: forward-level hist scan; warp 1: backward-level hist scan
    int wid = t >> 5, lane = t & 31;
    if (wid < 2) {
        const int* hist = wid ? g_bhist : g_fhist;
        int* off = wid ? g_boff : g_foff;
        int* cur = wid ? g_bcur : g_fcur;
        int hv = (lane < NLVL) ? hist[lane] : 0;
        int v = hv;
#pragma unroll
        for (int o = 1; o < 32; o <<= 1) {
            int n = __shfl_up_sync(0xffffffffu, v, o);
            if (lane >= o) v += n;
        }
        int excl = v - hv;
        if (lane < NLVL) { off[lane] = excl; cur[lane] = excl; }
        if (lane == NLVL) off[NLVL] = excl;   // total
    }
    if (t == 64) { g_in_ptr[NN] = EE; g_out_ptr[NN] = EE; }
}

// ---------------- K5: add block offsets, init scatter cursors ----------------
__global__ void k_scan3() {
    int stride = gridDim.x * blockDim.x;
    for (int i = blockIdx.x * blockDim.x + threadIdx.x; i < 2 * NN; i += stride) {
        if (i < NN) {
            int v = g_in_ptr[i] + g_bsum_s[0][i >> 10];
            g_in_ptr[i] = v;
            g_cur_in[i] = v;
        } else {
            int j = i - NN;
            int v = g_out_ptr[j] + g_bsum_s[1][j >> 10];
            g_out_ptr[j] = v;
            g_cur_out[j] = v;
        }
    }
}

// ---------------- K6: scatter edges into CSR/CSC, nodes into level lists ----------------
__global__ void k_scatter(const int* __restrict__ ei, const int* __restrict__ fl,
                          const int* __restrict__ bl) {
    int stride = gridDim.x * blockDim.x;
    for (int i = blockIdx.x * blockDim.x + threadIdx.x; i < EE; i += stride) {
        int src = ei[i], dst = ei[EE + i];
        int p = atomicAdd(&g_cur_in[dst], 1);
        g_csr_src[p] = src;
        int q = atomicAdd(&g_cur_out[src], 1);
        g_csc_dst[q] = dst;
        if (i < NN) {
            int pf = atomicAdd(&g_fcur[fl[i]], 1);
            g_fnodes[pf] = i;
            int pb = atomicAdd(&g_bcur[bl[i]], 1);
            g_bnodes[pb] = i;
        }
    }
}

// ---------------- grid-wide software barrier (persistent kernel) ----------------
__device__ __forceinline__ void grid_bar(unsigned target) {
    __threadfence();                    // release my writes (all threads)
    __syncthreads();
    if (threadIdx.x == 0) {
        unsigned t = atomicAdd(&g_cnt, 1u);
        if (t == (unsigned)gridDim.x - 1u) {
            g_cnt = 0u;
            __threadfence();
            g_gen = target;
        } else {
            while (g_gen != target) __nanosleep(64);
        }
        __threadfence();                // acquire
    }
    __syncthreads();
}

// ---------------- pool flush helper ----------------
__device__ __forceinline__ void pool_flush(int cb, float2 mx, float2 sm, int lane,
                                           float* out) {
    int d = 2 * lane;
    unsigned* uo = (unsigned*)out;
    atomicMax(&uo[cb * 128 + d], enc_f(mx.x));
    atomicMax(&uo[cb * 128 + d + 1], enc_f(mx.y));
    atomicAdd(&out[cb * 128 + 64 + d], sm.x);
    atomicAdd(&out[cb * 128 + 64 + d + 1], sm.y);
}

// ---------------- persistent kernel: all 22 level steps + pool + fixup ----------------
__global__ void __launch_bounds__(256, 2) k_levels(
    const int* __restrict__ nt, const int* __restrict__ batch,
    const float* __restrict__ W_f, const float* __restrict__ b_f,
    const float* __restrict__ W_b, const float* __restrict__ b_b,
    float* __restrict__ out) {

    __shared__ float sW[64][64];
    __shared__ float sA[64][68];
    __shared__ int sNode[64];
    __shared__ int sDeg[64];

    // barrier bookkeeping lives in thread 0 only
    unsigned base = 0, nbar = 0;
    if (threadIdx.x == 0) base = g_gen;

    const int lane = threadIdx.x & 31;
    const int gwarp = ((blockIdx.x * blockDim.x) + threadIdx.x) >> 5;
    const int nwarps = (gridDim.x * blockDim.x) >> 5;

    const int tx = threadIdx.x & 15, ty = threadIdx.x >> 4;
    const int n0 = tx << 2, m0 = ty << 2;

    for (int dir = 0; dir < 2; dir++) {
        const float* W = dir ? W_b : W_f;
        const float* bias = dir ? b_b : b_f;
        const int* off = dir ? g_boff : g_foff;
        const int* nodes = dir ? g_bnodes : g_fnodes;
        const int* ptr = dir ? g_out_ptr : g_in_ptr;
        const int* adj = dir ? g_csc_dst : g_csr_src;

        // load weight tile once per direction (block-local)
        for (int i = threadIdx.x; i < 4096; i += 256) sW[i >> 6][i & 63] = W[i];
        float4 bs = *(const float4*)(bias + n0);
        __syncthreads();

        for (int l = 1; l < NLVL; l++) {
            int start = off[l];
            int cnt = off[l + 1] - start;

            // ---- gather phase: agg[v] = sum_nbr h[nbr] (L2 reads via .cg) ----
            for (int w = gwarp; w < cnt; w += nwarps) {
                int v = nodes[start + w];
                int e0 = ptr[v], e1 = ptr[v + 1];
                float2 acc = make_float2(0.f, 0.f);
                for (int e = e0; e < e1; e++) {
                    int s = adj[e];
                    float2 t = __ldcg((const float2*)(g_h + (size_t)s * DD) + lane);
                    acc.x += t.x;
                    acc.y += t.y;
                }
                *((float2*)(g_agg + (size_t)v * DD) + lane) = acc;
            }
            grid_bar(base + (++nbar));

            // ---- GEMM phase: h[v] = agg[v] @ W + deg(v)*b ----
            int ntiles = (cnt + 63) >> 6;
            for (int tile = blockIdx.x; tile < ntiles; tile += gridDim.x) {
                int r = threadIdx.x >> 2;
                int cseg = (threadIdx.x & 3) << 4;
                int m = tile * 64 + r;
                int v = -1, deg = 0;
                if (m < cnt) {
                    v = nodes[start + m];
                    deg = ptr[v + 1] - ptr[v];
                }
                if ((threadIdx.x & 3) == 0) { sNode[r] = v; sDeg[r] = deg; }
                const float4* src4 =
                    (const float4*)(g_agg + (size_t)(v < 0 ? 0 : v) * DD + cseg);
#pragma unroll
                for (int i = 0; i < 4; i++) {
                    float4 val = (v >= 0) ? __ldcg(src4 + i)
                                          : make_float4(0.f, 0.f, 0.f, 0.f);
                    *((float4*)&sA[r][cseg + i * 4]) = val;
                }
                __syncthreads();

                float c[4][4];
#pragma unroll
                for (int i = 0; i < 4; i++)
#pragma unroll
                    for (int j = 0; j < 4; j++) c[i][j] = 0.f;

#pragma unroll 8
                for (int k = 0; k < 64; k++) {
                    float4 b4 = *((const float4*)&sW[k][n0]);
                    float a0 = sA[m0 + 0][k];
                    float a1 = sA[m0 + 1][k];
                    float a2 = sA[m0 + 2][k];
                    float a3 = sA[m0 + 3][k];
                    c[0][0] += a0 * b4.x; c[0][1] += a0 * b4.y; c[0][2] += a0 * b4.z; c[0][3] += a0 * b4.w;
                    c[1][0] += a1 * b4.x; c[1][1] += a1 * b4.y; c[1][2] += a1 * b4.z; c[1][3] += a1 * b4.w;
                    c[2][0] += a2 * b4.x; c[2][1] += a2 * b4.y; c[2][2] += a2 * b4.z; c[2][3] += a2 * b4.w;
                    c[3][0] += a3 * b4.x; c[3][1] += a3 * b4.y; c[3][2] += a3 * b4.z; c[3][3] += a3 * b4.w;
                }

#pragma unroll
                for (int i = 0; i < 4; i++) {
                    int v2 = sNode[m0 + i];
                    if (v2 >= 0) {
                        float dg = (float)sDeg[m0 + i];
                        float4 o;
                        o.x = c[i][0] + dg * bs.x;
                        o.y = c[i][1] + dg * bs.y;
                        o.z = c[i][2] + dg * bs.z;
                        o.w = c[i][3] + dg * bs.w;
                        *((float4*)(g_h + (size_t)v2 * DD + n0)) = o;
                    }
                }
                __syncthreads();
            }
            grid_bar(base + (++nbar));
        }
    }

    // ---- pool phase ----
    {
        int chunk = (NN + gridDim.x - 1) / gridDim.x;
        int s = blockIdx.x * chunk;
        int e = min(NN, s + chunk);
        if (s < e) {
            int warp = threadIdx.x >> 5;
            int nw = blockDim.x >> 5;
            int len = e - s;
            int wchunk = (len + nw - 1) / nw;
            int ws = s + warp * wchunk;
            int we = min(e, ws + wchunk);
            float2 mx = make_float2(NEGMAX, NEGMAX);
            float2 sm = make_float2(0.f, 0.f);
            int cb = (ws < we) ? batch[ws] : -1;
            for (int n = ws; n < we; n++) {
                int bb = batch[n];
                if (bb != cb) {
                    pool_flush(cb, mx, sm, lane, out);
                    mx = make_float2(NEGMAX, NEGMAX);
                    sm = make_float2(0.f, 0.f);
                    cb = bb;
                }
                if (nt[n] == 1) {
                    float2 v = __ldcg((const float2*)(g_h + (size_t)n * DD) + lane);
                    mx.x = fmaxf(mx.x, v.x);
                    mx.y = fmaxf(mx.y, v.y);
                    sm.x += v.x;
                    sm.y += v.y;
                }
            }
            if (cb >= 0) pool_flush(cb, mx, sm, lane, out);
        }
    }
    grid_bar(base + (++nbar));

    // ---- fixup: decode ordered-uint max half (block 0) ----
    if (blockIdx.x == 0) {
        for (int i = threadIdx.x; i < BBATCH * DD; i += 256) {
            int b = i >> 6, d = i & 63;
            int pos = b * 128 + d;
            unsigned u = __ldcg((const unsigned*)out + pos);
            out[pos] = dec_f(u);
        }
    }
}

// ---------------- launch ----------------
extern "C" void kernel_launch(void* const* d_in, const int* in_sizes, int n_in,
                              void* d_out, int out_size) {
    const int* nt    = (const int*)d_in[0];
    const int* nip   = (const int*)d_in[1];
    const int* ei    = (const int*)d_in[2];
    const int* fl    = (const int*)d_in[3];
    const int* bl    = (const int*)d_in[4];
    const int* batch = (const int*)d_in[5];
    const float* W_enc = (const float*)d_in[6];
    const float* b_enc = (const float*)d_in[7];
    const float* W_f   = (const float*)d_in[8];
    const float* b_f   = (const float*)d_in[9];
    const float* W_b   = (const float*)d_in[10];
    const float* b_b   = (const float*)d_in[11];
    float* out = (float*)d_out;

    k_init<<<2048, 256>>>(nt, nip, W_enc, b_enc, out);
    k_deg<<<1600, 256>>>(ei, fl, bl);
    k_scan1<<<2 * SCAN_NB, 256>>>();
    k_scan2p<<<1, 256>>>();
    k_scan3<<<784, 256>>>();
    k_scatter<<<1600, 256>>>(ei, fl, bl);
    k_levels<<<PGRID, 256>>>(nt, batch, W_f, b_f, W_b, b_b, out);
}

// round 4
// speedup vs baseline: 1.1471x; 1.1471x over previous
#include <cuda_runtime.h>

#define NN 200000
#define EE 400000
#define DD 64
#define BBATCH 16
#define NLVL 12
#define SCAN_NB ((NN + 1023) / 1024)   // 196

// ---------------- device scratch ----------------
__device__ float g_h[NN * DD];          // node states (node-indexed)
__device__ float g_agg[NN * DD];        // gathered sums (SLOT-indexed)
__device__ int g_indeg[NN], g_outdeg[NN];
__device__ int g_fnodes[NN], g_bnodes[NN];   // slot -> node
__device__ int g_fslot[NN], g_bslot[NN];     // node -> slot
__device__ int g_fdeg[NN], g_bdeg[NN];       // slot-indexed degree
__device__ int g_feptr[NN + 1], g_beptr[NN + 1];  // slot-indexed edge ptr
__device__ int g_fcur_e[NN], g_bcur_e[NN];   // edge scatter cursors
__device__ int g_fsrc[EE];              // forward: sources grouped by dst-slot
__device__ int g_bdst[EE];              // backward: dsts grouped by src-slot
__device__ int g_fhist[NLVL], g_bhist[NLVL];
__device__ int g_foff[NLVL + 1], g_boff[NLVL + 1];
__device__ int g_fcur[NLVL], g_bcur[NLVL];
__device__ int g_bsum[2][SCAN_NB], g_bsum_s[2][SCAN_NB];

__device__ __forceinline__ unsigned enc_f(float f) {
    unsigned u = __float_as_uint(f);
    return (u & 0x80000000u) ? ~u : (u | 0x80000000u);
}
__device__ __forceinline__ float dec_f(unsigned u) {
    return (u & 0x80000000u) ? __uint_as_float(u & 0x7FFFFFFFu)
                             : __uint_as_float(~u);
}
#define NEGMAX (-3.402823466e38f)

// ---------------- K1: init h (float4), zero counters, init output ----------------
__global__ void k_init(const int* __restrict__ nt, const int* __restrict__ nip,
                       const float* __restrict__ Wenc, const float* __restrict__ benc,
                       float* __restrict__ out) {
    int stride = gridDim.x * blockDim.x;
    for (int q = blockIdx.x * blockDim.x + threadIdx.x; q < NN * DD / 4; q += stride) {
        int n = q >> 4;
        int d = (q & 15) << 2;
        float a = (float)nt[n], b = (float)nip[n];
        float4 w0 = *(const float4*)(Wenc + d);
        float4 w1 = *(const float4*)(Wenc + 64 + d);
        float4 be = *(const float4*)(benc + d);
        float4 o;
        o.x = a * w0.x + b * w1.x + be.x;
        o.y = a * w0.y + b * w1.y + be.y;
        o.z = a * w0.z + b * w1.z + be.z;
        o.w = a * w0.w + b * w1.w + be.w;
        *(float4*)(g_h + (size_t)q * 4) = o;
        if (q < NN) { g_indeg[q] = 0; g_outdeg[q] = 0; }
        if (q < NLVL) { g_fhist[q] = 0; g_bhist[q] = 0; }
        if (q < BBATCH * 2 * DD) {
            int col = q & 127;
            ((unsigned*)out)[q] = (col < 64) ? 0x00800000u : 0u;
        }
    }
}

// ---------------- K2: degrees + level histograms ----------------
__global__ void k_deg(const int* __restrict__ ei, const int* __restrict__ fl,
                      const int* __restrict__ bl) {
    int stride = gridDim.x * blockDim.x;
    for (int i = blockIdx.x * blockDim.x + threadIdx.x; i < EE; i += stride) {
        atomicAdd(&g_indeg[ei[EE + i]], 1);   // dst
        atomicAdd(&g_outdeg[ei[i]], 1);       // src
        if (i < NN) {
            atomicAdd(&g_fhist[fl[i]], 1);
            atomicAdd(&g_bhist[bl[i]], 1);
        }
    }
}

// ---------------- K3: tiny scan of level hists -> foff/boff ----------------
__global__ void k_histscan() {
    int t = threadIdx.x;
    int wid = t >> 5, lane = t & 31;
    if (wid < 2) {
        const int* hist = wid ? g_bhist : g_fhist;
        int* off = wid ? g_boff : g_foff;
        int* cur = wid ? g_bcur : g_fcur;
        int hv = (lane < NLVL) ? hist[lane] : 0;
        int v = hv;
#pragma unroll
        for (int o = 1; o < 32; o <<= 1) {
            int n = __shfl_up_sync(0xffffffffu, v, o);
            if (lane >= o) v += n;
        }
        int excl = v - hv;
        if (lane < NLVL) { off[lane] = excl; cur[lane] = excl; }
        if (lane == NLVL) off[NLVL] = excl;
    }
}

// ---------------- K4: assign slots (level-ordered), record slot degrees ----------------
__global__ void k_assign(const int* __restrict__ fl, const int* __restrict__ bl) {
    int stride = gridDim.x * blockDim.x;
    for (int v = blockIdx.x * blockDim.x + threadIdx.x; v < NN; v += stride) {
        int s = atomicAdd(&g_fcur[fl[v]], 1);
        g_fnodes[s] = v;
        g_fslot[v] = s;
        g_fdeg[s] = g_indeg[v];
        int s2 = atomicAdd(&g_bcur[bl[v]], 1);
        g_bnodes[s2] = v;
        g_bslot[v] = s2;
        g_bdeg[s2] = g_outdeg[v];
    }
}

// ---------------- K5: block-local exclusive scans of slot degrees ----------------
__global__ void k_scan1() {
    int which = blockIdx.x / SCAN_NB;   // 0 = fdeg, 1 = bdeg
    int blk = blockIdx.x % SCAN_NB;
    const int* deg = which ? g_bdeg : g_fdeg;
    int* ptr = which ? g_beptr : g_feptr;
    __shared__ int sh[256];
    int base = blk * 1024 + threadIdx.x * 4;
    int v[4];
    int s = 0;
#pragma unroll
    for (int j = 0; j < 4; j++) {
        int idx = base + j;
        v[j] = (idx < NN) ? deg[idx] : 0;
        s += v[j];
    }
    sh[threadIdx.x] = s;
    __syncthreads();
    for (int off = 1; off < 256; off <<= 1) {
        int t = 0;
        if (threadIdx.x >= off) t = sh[threadIdx.x - off];
        __syncthreads();
        sh[threadIdx.x] += t;
        __syncthreads();
    }
    int run = sh[threadIdx.x] - s;
#pragma unroll
    for (int j = 0; j < 4; j++) {
        int idx = base + j;
        if (idx < NN) ptr[idx] = run;
        run += v[j];
    }
    if (threadIdx.x == 255) g_bsum[which][blk] = sh[255];
}

// ---------------- K6: scan of block sums ----------------
__global__ void k_scan2p() {
    __shared__ int sh[256];
    int t = threadIdx.x;
#pragma unroll
    for (int w = 0; w < 2; w++) {
        int v = (t < SCAN_NB) ? g_bsum[w][t] : 0;
        sh[t] = v;
        __syncthreads();
        for (int off = 1; off < 256; off <<= 1) {
            int x = 0;
            if (t >= off) x = sh[t - off];
            __syncthreads();
            sh[t] += x;
            __syncthreads();
        }
        if (t < SCAN_NB) g_bsum_s[w][t] = sh[t] - v;
        __syncthreads();
    }
    if (t == 0) { g_feptr[NN] = EE; g_beptr[NN] = EE; }
}

// ---------------- K7: add block offsets, init edge-scatter cursors ----------------
__global__ void k_scan3() {
    int stride = gridDim.x * blockDim.x;
    for (int i = blockIdx.x * blockDim.x + threadIdx.x; i < 2 * NN; i += stride) {
        if (i < NN) {
            int v = g_feptr[i] + g_bsum_s[0][i >> 10];
            g_feptr[i] = v;
            g_fcur_e[i] = v;
        } else {
            int j = i - NN;
            int v = g_beptr[j] + g_bsum_s[1][j >> 10];
            g_beptr[j] = v;
            g_bcur_e[j] = v;
        }
    }
}

// ---------------- K8: scatter edges into slot-ordered lists ----------------
__global__ void k_scatter_e(const int* __restrict__ ei) {
    int stride = gridDim.x * blockDim.x;
    for (int i = blockIdx.x * blockDim.x + threadIdx.x; i < EE; i += stride) {
        int src = ei[i], dst = ei[EE + i];
        int sf = g_fslot[dst];
        int p = atomicAdd(&g_fcur_e[sf], 1);
        g_fsrc[p] = src;
        int sb = g_bslot[src];
        int q = atomicAdd(&g_bcur_e[sb], 1);
        g_bdst[q] = dst;
    }
}

// ---------------- per-level gather: agg[slot] = sum of h[src] ----------------
__global__ void k_gather(int level, int dir) {
    const int* off  = dir ? g_boff : g_foff;
    const int* eptr = dir ? g_beptr : g_feptr;
    const int* esrc = dir ? g_bdst : g_fsrc;
    int start = off[level];
    int cnt = off[level + 1] - start;
    int wid = (blockIdx.x * blockDim.x + threadIdx.x) >> 5;
    int lane = threadIdx.x & 31;
    int nwarps = (gridDim.x * blockDim.x) >> 5;
    for (int s = wid; s < cnt; s += nwarps) {
        int slot = start + s;
        int e0 = __ldg(eptr + slot), e1 = __ldg(eptr + slot + 1);
        float2 acc = make_float2(0.f, 0.f);
        for (int e = e0; e < e1; e++) {
            int src = __ldg(esrc + e);
            float2 t = *((const float2*)(g_h + (size_t)src * DD) + lane);
            acc.x += t.x;
            acc.y += t.y;
        }
        *((float2*)(g_agg + (size_t)slot * DD) + lane) = acc;
    }
}

// ---------------- per-level GEMM: h[node(slot)] = agg[slot] @ W + deg*b ----------------
__global__ void __launch_bounds__(256) k_gemm(int level, int dir,
                                              const float* __restrict__ W,
                                              const float* __restrict__ bias) {
    __shared__ float sW[64][64];
    __shared__ float sA[64][68];
    const int* off   = dir ? g_boff : g_foff;
    const int* nodes = dir ? g_bnodes : g_fnodes;
    const int* deg   = dir ? g_bdeg : g_fdeg;
    int start = off[level];
    int cnt = off[level + 1] - start;
    int ntiles = (cnt + 63) >> 6;

    for (int i = threadIdx.x; i < 4096; i += 256) sW[i >> 6][i & 63] = W[i];

    int tx = threadIdx.x & 15, ty = threadIdx.x >> 4;
    int n0 = tx << 2, m0 = ty << 2;
    float4 bs = *(const float4*)(bias + n0);

    for (int tile = blockIdx.x; tile < ntiles; tile += gridDim.x) {
        int r = threadIdx.x >> 2;             // row within tile
        int cseg = (threadIdx.x & 3) << 4;    // 16-float segment
        int m = tile * 64 + r;
        // dense slot-indexed A load
        const float4* src4 =
            (const float4*)(g_agg + (size_t)(start + (m < cnt ? m : 0)) * DD + cseg);
#pragma unroll
        for (int i = 0; i < 4; i++) {
            float4 val = (m < cnt) ? src4[i] : make_float4(0.f, 0.f, 0.f, 0.f);
            *((float4*)&sA[r][cseg + i * 4]) = val;
        }
        __syncthreads();

        float c[4][4];
#pragma unroll
        for (int i = 0; i < 4; i++)
#pragma unroll
            for (int j = 0; j < 4; j++) c[i][j] = 0.f;

#pragma unroll 8
        for (int k = 0; k < 64; k++) {
            float4 b4 = *((const float4*)&sW[k][n0]);
            float a0 = sA[m0 + 0][k];
            float a1 = sA[m0 + 1][k];
            float a2 = sA[m0 + 2][k];
            float a3 = sA[m0 + 3][k];
            c[0][0] += a0 * b4.x; c[0][1] += a0 * b4.y; c[0][2] += a0 * b4.z; c[0][3] += a0 * b4.w;
            c[1][0] += a1 * b4.x; c[1][1] += a1 * b4.y; c[1][2] += a1 * b4.z; c[1][3] += a1 * b4.w;
            c[2][0] += a2 * b4.x; c[2][1] += a2 * b4.y; c[2][2] += a2 * b4.z; c[2][3] += a2 * b4.w;
            c[3][0] += a3 * b4.x; c[3][1] += a3 * b4.y; c[3][2] += a3 * b4.z; c[3][3] += a3 * b4.w;
        }

#pragma unroll
        for (int i = 0; i < 4; i++) {
            int mm = tile * 64 + m0 + i;
            if (mm < cnt) {
                int slot = start + mm;
                int v = __ldg(nodes + slot);       // contiguous, L1-broadcast
                float dg = (float)__ldg(deg + slot);
                float4 o;
                o.x = c[i][0] + dg * bs.x;
                o.y = c[i][1] + dg * bs.y;
                o.z = c[i][2] + dg * bs.z;
                o.w = c[i][3] + dg * bs.w;
                *((float4*)(g_h + (size_t)v * DD + n0)) = o;
            }
        }
        __syncthreads();
    }
}

// ---------------- readout ----------------
__device__ __forceinline__ void pool_flush(int cb, float2 mx, float2 sm, int lane,
                                           float* out) {
    int d = 2 * lane;
    unsigned* uo = (unsigned*)out;
    atomicMax(&uo[cb * 128 + d], enc_f(mx.x));
    atomicMax(&uo[cb * 128 + d + 1], enc_f(mx.y));
    atomicAdd(&out[cb * 128 + 64 + d], sm.x);
    atomicAdd(&out[cb * 128 + 64 + d + 1], sm.y);
}

__global__ void k_pool(const int* __restrict__ nt, const int* __restrict__ batch,
                       float* __restrict__ out) {
    int chunk = (NN + gridDim.x - 1) / gridDim.x;
    int s = blockIdx.x * chunk;
    int e = min(NN, s + chunk);
    if (s >= e) return;
    int warp = threadIdx.x >> 5, lane = threadIdx.x & 31;
    int nw = blockDim.x >> 5;
    int len = e - s;
    int wchunk = (len + nw - 1) / nw;
    int ws = s + warp * wchunk;
    int we = min(e, ws + wchunk);
    float2 mx = make_float2(NEGMAX, NEGMAX);
    float2 sm = make_float2(0.f, 0.f);
    int cb = (ws < we) ? batch[ws] : -1;
    for (int n = ws; n < we; n++) {
        int bb = batch[n];
        if (bb != cb) {
            pool_flush(cb, mx, sm, lane, out);
            mx = make_float2(NEGMAX, NEGMAX);
            sm = make_float2(0.f, 0.f);
            cb = bb;
        }
        if (nt[n] == 1) {
            float2 v = *((const float2*)(g_h + (size_t)n * DD) + lane);
            mx.x = fmaxf(mx.x, v.x);
            mx.y = fmaxf(mx.y, v.y);
            sm.x += v.x;
            sm.y += v.y;
        }
    }
    if (cb >= 0) pool_flush(cb, mx, sm, lane, out);
}

__global__ void k_fixup(float* __restrict__ out) {
    int i = threadIdx.x;           // 1024 = B*64
    int b = i >> 6, d = i & 63;
    int pos = b * 128 + d;
    unsigned u = ((unsigned*)out)[pos];
    out[pos] = dec_f(u);
}

// ---------------- launch ----------------
extern "C" void kernel_launch(void* const* d_in, const int* in_sizes, int n_in,
                              void* d_out, int out_size) {
    const int* nt    = (const int*)d_in[0];
    const int* nip   = (const int*)d_in[1];
    const int* ei    = (const int*)d_in[2];
    const int* fl    = (const int*)d_in[3];
    const int* bl    = (const int*)d_in[4];
    const int* batch = (const int*)d_in[5];
    const float* W_enc = (const float*)d_in[6];
    const float* b_enc = (const float*)d_in[7];
    const float* W_f   = (const float*)d_in[8];
    const float* b_f   = (const float*)d_in[9];
    const float* W_b   = (const float*)d_in[10];
    const float* b_b   = (const float*)d_in[11];
    float* out = (float*)d_out;

    k_init<<<2048, 256>>>(nt, nip, W_enc, b_enc, out);
    k_deg<<<1600, 256>>>(ei, fl, bl);
    k_histscan<<<1, 64>>>();
    k_assign<<<784, 256>>>(fl, bl);
    k_scan1<<<2 * SCAN_NB, 256>>>();
    k_scan2p<<<1, 256>>>();
    k_scan3<<<784, 256>>>();
    k_scatter_e<<<1600, 256>>>(ei);

    for (int l = 1; l < NLVL; l++) {
        k_gather<<<2048, 256>>>(l, 0);
        k_gemm<<<320, 256>>>(l, 0, W_f, b_f);
    }
    for (int l = 1; l < NLVL; l++) {
        k_gather<<<2048, 256>>>(l, 1);
        k_gemm<<<320, 256>>>(l, 1, W_b, b_b);
    }

    k_pool<<<592, 256>>>(nt, batch, out);
    k_fixup<<<1, 1024>>>(out);
}

// round 5
// speedup vs baseline: 1.4024x; 1.2226x over previous
#include <cuda_runtime.h>

#define NN 200000
#define EE 400000
#define DD 64
#define BBATCH 16
#define NLVL 12
#define SCAN_NB ((NN + 1023) / 1024)   // 196
#define HB SCAN_NB                     // histogram blocks (1024 nodes each)

// ---------------- device scratch ----------------
__device__ float g_h[NN * DD];          // node states (node-indexed)
__device__ float g_agg[NN * DD];        // gathered sums (SLOT-indexed)
__device__ int g_indeg[NN], g_outdeg[NN];
__device__ int g_fnodes[NN], g_bnodes[NN];   // slot -> node
__device__ int g_fslot[NN], g_bslot[NN];     // node -> slot
__device__ int g_fdeg[NN], g_bdeg[NN];       // slot-indexed degree
__device__ int g_feptr[NN + 1], g_beptr[NN + 1];  // slot-indexed edge ptr
__device__ int g_fcur_e[NN], g_bcur_e[NN];   // edge scatter cursors
__device__ int g_fsrc[EE];              // forward: sources grouped by dst-slot
__device__ int g_bdst[EE];              // backward: dsts grouped by src-slot
__device__ int g_foff[NLVL + 1], g_boff[NLVL + 1];
__device__ int g_lhist[2 * NLVL * HB];  // [dir][lvl][blk] counts -> offsets
__device__ int g_bsum[2][SCAN_NB], g_bsum_s[2][SCAN_NB];

__device__ __forceinline__ unsigned enc_f(float f) {
    unsigned u = __float_as_uint(f);
    return (u & 0x80000000u) ? ~u : (u | 0x80000000u);
}
__device__ __forceinline__ float dec_f(unsigned u) {
    return (u & 0x80000000u) ? __uint_as_float(u & 0x7FFFFFFFu)
                             : __uint_as_float(~u);
}
#define NEGMAX (-3.402823466e38f)

// ---------------- K1: init h (float4), zero counters, init output ----------------
__global__ void k_init(const int* __restrict__ nt, const int* __restrict__ nip,
                       const float* __restrict__ Wenc, const float* __restrict__ benc,
                       float* __restrict__ out) {
    int stride = gridDim.x * blockDim.x;
    for (int q = blockIdx.x * blockDim.x + threadIdx.x; q < NN * DD / 4; q += stride) {
        int n = q >> 4;
        int d = (q & 15) << 2;
        float a = (float)nt[n], b = (float)nip[n];
        float4 w0 = *(const float4*)(Wenc + d);
        float4 w1 = *(const float4*)(Wenc + 64 + d);
        float4 be = *(const float4*)(benc + d);
        float4 o;
        o.x = a * w0.x + b * w1.x + be.x;
        o.y = a * w0.y + b * w1.y + be.y;
        o.z = a * w0.z + b * w1.z + be.z;
        o.w = a * w0.w + b * w1.w + be.w;
        *(float4*)(g_h + (size_t)q * 4) = o;
        if (q < NN) { g_indeg[q] = 0; g_outdeg[q] = 0; }
        if (q < BBATCH * 2 * DD) {
            int col = q & 127;
            ((unsigned*)out)[q] = (col < 64) ? 0x00800000u : 0u;
        }
    }
}

// ---------------- K2: degrees only (spread atomics, fast path) ----------------
__global__ void k_deg(const int* __restrict__ ei) {
    int stride = gridDim.x * blockDim.x;
    for (int i = blockIdx.x * blockDim.x + threadIdx.x; i < EE; i += stride) {
        atomicAdd(&g_indeg[ei[EE + i]], 1);   // dst
        atomicAdd(&g_outdeg[ei[i]], 1);       // src
    }
}

// ---------------- K3: per-block level histograms (smem, no L2 hotspots) ----------------
__global__ void k_hist(const int* __restrict__ fl, const int* __restrict__ bl) {
    __shared__ int sh[2 * NLVL];
    int t = threadIdx.x;
    if (t < 2 * NLVL) sh[t] = 0;
    __syncthreads();
    int base = blockIdx.x * 1024;
#pragma unroll
    for (int j = 0; j < 4; j++) {
        int idx = base + j * 256 + t;
        if (idx < NN) {
            atomicAdd(&sh[fl[idx]], 1);
            atomicAdd(&sh[NLVL + bl[idx]], 1);
        }
    }
    __syncthreads();
    if (t < 2 * NLVL) {
        // layout: [dir*NLVL + lvl] * HB + blk
        g_lhist[t * HB + blockIdx.x] = sh[t];
    }
}

// ---------------- K4: scan block hists -> per-(blk,lvl) offsets + foff/boff ----------------
__global__ void k_hscan() {
    __shared__ int tot[2 * NLVL];
    __shared__ int off_s[2][NLVL + 1];
    int t = threadIdx.x;
    int wid = t >> 5, lane = t & 31;       // 24 warps
    int* row = g_lhist + wid * HB;
    // exclusive scan over the 196 block counts of this (dir,lvl)
    int carry = 0;
#pragma unroll
    for (int r = 0; r < (HB + 31) / 32; r++) {
        int idx = r * 32 + lane;
        int v = (idx < HB) ? row[idx] : 0;
        int incl = v;
#pragma unroll
        for (int o = 1; o < 32; o <<= 1) {
            int n = __shfl_up_sync(0xffffffffu, incl, o);
            if (lane >= o) incl += n;
        }
        if (idx < HB) row[idx] = incl - v + carry;
        carry += __shfl_sync(0xffffffffu, incl, 31);
    }
    if (lane == 0) tot[wid] = carry;
    __syncthreads();
    // warps 0,1: scan the 12 level totals -> foff/boff
    if (wid < 2) {
        int hv = (lane < NLVL) ? tot[wid * NLVL + lane] : 0;
        int v = hv;
#pragma unroll
        for (int o = 1; o < 32; o <<= 1) {
            int n = __shfl_up_sync(0xffffffffu, v, o);
            if (lane >= o) v += n;
        }
        int excl = v - hv;
        if (lane <= NLVL) {
            off_s[wid][lane] = excl;
            (wid ? g_boff : g_foff)[lane] = excl;
        }
    }
    __syncthreads();
    // add level base to each block offset
    int add = off_s[wid / NLVL][wid % NLVL];
#pragma unroll
    for (int r = 0; r < (HB + 31) / 32; r++) {
        int idx = r * 32 + lane;
        if (idx < HB) row[idx] += add;
    }
}

// ---------------- K5: assign slots via block-local smem counters ----------------
__global__ void k_assign2(const int* __restrict__ fl, const int* __restrict__ bl) {
    __shared__ int sc[2 * NLVL];
    int t = threadIdx.x;
    if (t < 2 * NLVL) sc[t] = g_lhist[t * HB + blockIdx.x];
    __syncthreads();
    int base = blockIdx.x * 1024;
#pragma unroll
    for (int j = 0; j < 4; j++) {
        int v = base + j * 256 + t;
        if (v < NN) {
            int s = atomicAdd(&sc[fl[v]], 1);
            g_fnodes[s] = v;
            g_fslot[v] = s;
            g_fdeg[s] = g_indeg[v];
            int s2 = atomicAdd(&sc[NLVL + bl[v]], 1);
            g_bnodes[s2] = v;
            g_bslot[v] = s2;
            g_bdeg[s2] = g_outdeg[v];
        }
    }
}

// ---------------- K6: block-local exclusive scans of slot degrees ----------------
__global__ void k_scan1() {
    int which = blockIdx.x / SCAN_NB;   // 0 = fdeg, 1 = bdeg
    int blk = blockIdx.x % SCAN_NB;
    const int* deg = which ? g_bdeg : g_fdeg;
    int* ptr = which ? g_beptr : g_feptr;
    __shared__ int sh[256];
    int base = blk * 1024 + threadIdx.x * 4;
    int v[4];
    int s = 0;
#pragma unroll
    for (int j = 0; j < 4; j++) {
        int idx = base + j;
        v[j] = (idx < NN) ? deg[idx] : 0;
        s += v[j];
    }
    sh[threadIdx.x] = s;
    __syncthreads();
    for (int off = 1; off < 256; off <<= 1) {
        int t = 0;
        if (threadIdx.x >= off) t = sh[threadIdx.x - off];
        __syncthreads();
        sh[threadIdx.x] += t;
        __syncthreads();
    }
    int run = sh[threadIdx.x] - s;
#pragma unroll
    for (int j = 0; j < 4; j++) {
        int idx = base + j;
        if (idx < NN) ptr[idx] = run;
        run += v[j];
    }
    if (threadIdx.x == 255) g_bsum[which][blk] = sh[255];
}

// ---------------- K7: scan of block sums ----------------
__global__ void k_scan2p() {
    __shared__ int sh[256];
    int t = threadIdx.x;
#pragma unroll
    for (int w = 0; w < 2; w++) {
        int v = (t < SCAN_NB) ? g_bsum[w][t] : 0;
        sh[t] = v;
        __syncthreads();
        for (int off = 1; off < 256; off <<= 1) {
            int x = 0;
            if (t >= off) x = sh[t - off];
            __syncthreads();
            sh[t] += x;
            __syncthreads();
        }
        if (t < SCAN_NB) g_bsum_s[w][t] = sh[t] - v;
        __syncthreads();
    }
    if (t == 0) { g_feptr[NN] = EE; g_beptr[NN] = EE; }
}

// ---------------- K8: add block offsets, init edge-scatter cursors ----------------
__global__ void k_scan3() {
    int stride = gridDim.x * blockDim.x;
    for (int i = blockIdx.x * blockDim.x + threadIdx.x; i < 2 * NN; i += stride) {
        if (i < NN) {
            int v = g_feptr[i] + g_bsum_s[0][i >> 10];
            g_feptr[i] = v;
            g_fcur_e[i] = v;
        } else {
            int j = i - NN;
            int v = g_beptr[j] + g_bsum_s[1][j >> 10];
            g_beptr[j] = v;
            g_bcur_e[j] = v;
        }
    }
}

// ---------------- K9: scatter edges into slot-ordered lists ----------------
__global__ void k_scatter_e(const int* __restrict__ ei) {
    int stride = gridDim.x * blockDim.x;
    for (int i = blockIdx.x * blockDim.x + threadIdx.x; i < EE; i += stride) {
        int src = ei[i], dst = ei[EE + i];
        int sf = g_fslot[dst];
        int p = atomicAdd(&g_fcur_e[sf], 1);
        g_fsrc[p] = src;
        int sb = g_bslot[src];
        int q = atomicAdd(&g_bcur_e[sb], 1);
        g_bdst[q] = dst;
    }
}

// ---------------- per-level gather: agg[slot] = sum of h[src] ----------------
__global__ void k_gather(int level, int dir) {
    const int* off  = dir ? g_boff : g_foff;
    const int* eptr = dir ? g_beptr : g_feptr;
    const int* esrc = dir ? g_bdst : g_fsrc;
    int start = off[level];
    int cnt = off[level + 1] - start;
    int wid = (blockIdx.x * blockDim.x + threadIdx.x) >> 5;
    int lane = threadIdx.x & 31;
    int nwarps = (gridDim.x * blockDim.x) >> 5;
    for (int s = wid; s < cnt; s += nwarps) {
        int slot = start + s;
        int e0 = __ldg(eptr + slot), e1 = __ldg(eptr + slot + 1);
        float2 acc = make_float2(0.f, 0.f);
        for (int e = e0; e < e1; e++) {
            int src = __ldg(esrc + e);
            float2 t = *((const float2*)(g_h + (size_t)src * DD) + lane);
            acc.x += t.x;
            acc.y += t.y;
        }
        *((float2*)(g_agg + (size_t)slot * DD) + lane) = acc;
    }
}

// ---------------- per-level GEMM: h[node(slot)] = agg[slot] @ W + deg*b ----------------
__global__ void __launch_bounds__(256) k_gemm(int level, int dir,
                                              const float* __restrict__ W,
                                              const float* __restrict__ bias) {
    __shared__ float sW[64][64];
    __shared__ float sA[64][68];
    const int* off   = dir ? g_boff : g_foff;
    const int* nodes = dir ? g_bnodes : g_fnodes;
    const int* deg   = dir ? g_bdeg : g_fdeg;
    int start = off[level];
    int cnt = off[level + 1] - start;
    int ntiles = (cnt + 63) >> 6;

    for (int i = threadIdx.x; i < 4096; i += 256) sW[i >> 6][i & 63] = W[i];

    int tx = threadIdx.x & 15, ty = threadIdx.x >> 4;
    int n0 = tx << 2, m0 = ty << 2;
    float4 bs = *(const float4*)(bias + n0);

    for (int tile = blockIdx.x; tile < ntiles; tile += gridDim.x) {
        int r = threadIdx.x >> 2;
        int cseg = (threadIdx.x & 3) << 4;
        int m = tile * 64 + r;
        const float4* src4 =
            (const float4*)(g_agg + (size_t)(start + (m < cnt ? m : 0)) * DD + cseg);
#pragma unroll
        for (int i = 0; i < 4; i++) {
            float4 val = (m < cnt) ? src4[i] : make_float4(0.f, 0.f, 0.f, 0.f);
            *((float4*)&sA[r][cseg + i * 4]) = val;
        }
        __syncthreads();

        float c[4][4];
#pragma unroll
        for (int i = 0; i < 4; i++)
#pragma unroll
            for (int j = 0; j < 4; j++) c[i][j] = 0.f;

#pragma unroll 8
        for (int k = 0; k < 64; k++) {
            float4 b4 = *((const float4*)&sW[k][n0]);
            float a0 = sA[m0 + 0][k];
            float a1 = sA[m0 + 1][k];
            float a2 = sA[m0 + 2][k];
            float a3 = sA[m0 + 3][k];
            c[0][0] += a0 * b4.x; c[0][1] += a0 * b4.y; c[0][2] += a0 * b4.z; c[0][3] += a0 * b4.w;
            c[1][0] += a1 * b4.x; c[1][1] += a1 * b4.y; c[1][2] += a1 * b4.z; c[1][3] += a1 * b4.w;
            c[2][0] += a2 * b4.x; c[2][1] += a2 * b4.y; c[2][2] += a2 * b4.z; c[2][3] += a2 * b4.w;
            c[3][0] += a3 * b4.x; c[3][1] += a3 * b4.y; c[3][2] += a3 * b4.z; c[3][3] += a3 * b4.w;
        }

#pragma unroll
        for (int i = 0; i < 4; i++) {
            int mm = tile * 64 + m0 + i;
            if (mm < cnt) {
                int slot = start + mm;
                int v = __ldg(nodes + slot);
                float dg = (float)__ldg(deg + slot);
                float4 o;
                o.x = c[i][0] + dg * bs.x;
                o.y = c[i][1] + dg * bs.y;
                o.z = c[i][2] + dg * bs.z;
                o.w = c[i][3] + dg * bs.w;
                *((float4*)(g_h + (size_t)v * DD + n0)) = o;
            }
        }
        __syncthreads();
    }
}

// ---------------- readout ----------------
__device__ __forceinline__ void pool_flush(int cb, float2 mx, float2 sm, int lane,
                                           float* out) {
    int d = 2 * lane;
    unsigned* uo = (unsigned*)out;
    atomicMax(&uo[cb * 128 + d], enc_f(mx.x));
    atomicMax(&uo[cb * 128 + d + 1], enc_f(mx.y));
    atomicAdd(&out[cb * 128 + 64 + d], sm.x);
    atomicAdd(&out[cb * 128 + 64 + d + 1], sm.y);
}

__global__ void k_pool(const int* __restrict__ nt, const int* __restrict__ batch,
                       float* __restrict__ out) {
    int chunk = (NN + gridDim.x - 1) / gridDim.x;
    int s = blockIdx.x * chunk;
    int e = min(NN, s + chunk);
    if (s >= e) return;
    int warp = threadIdx.x >> 5, lane = threadIdx.x & 31;
    int nw = blockDim.x >> 5;
    int len = e - s;
    int wchunk = (len + nw - 1) / nw;
    int ws = s + warp * wchunk;
    int we = min(e, ws + wchunk);
    float2 mx = make_float2(NEGMAX, NEGMAX);
    float2 sm = make_float2(0.f, 0.f);
    int cb = (ws < we) ? batch[ws] : -1;
    for (int n = ws; n < we; n++) {
        int bb = batch[n];
        if (bb != cb) {
            pool_flush(cb, mx, sm, lane, out);
            mx = make_float2(NEGMAX, NEGMAX);
            sm = make_float2(0.f, 0.f);
            cb = bb;
        }
        if (nt[n] == 1) {
            float2 v = *((const float2*)(g_h + (size_t)n * DD) + lane);
            mx.x = fmaxf(mx.x, v.x);
            mx.y = fmaxf(mx.y, v.y);
            sm.x += v.x;
            sm.y += v.y;
        }
    }
    if (cb >= 0) pool_flush(cb, mx, sm, lane, out);
}

__global__ void k_fixup(float* __restrict__ out) {
    int i = threadIdx.x;           // 1024 = B*64
    int b = i >> 6, d = i & 63;
    int pos = b * 128 + d;
    unsigned u = ((unsigned*)out)[pos];
    out[pos] = dec_f(u);
}

// ---------------- launch ----------------
extern "C" void kernel_launch(void* const* d_in, const int* in_sizes, int n_in,
                              void* d_out, int out_size) {
    const int* nt    = (const int*)d_in[0];
    const int* nip   = (const int*)d_in[1];
    const int* ei    = (const int*)d_in[2];
    const int* fl    = (const int*)d_in[3];
    const int* bl    = (const int*)d_in[4];
    const int* batch = (const int*)d_in[5];
    const float* W_enc = (const float*)d_in[6];
    const float* b_enc = (const float*)d_in[7];
    const float* W_f   = (const float*)d_in[8];
    const float* b_f   = (const float*)d_in[9];
    const float* W_b   = (const float*)d_in[10];
    const float* b_b   = (const float*)d_in[11];
    float* out = (float*)d_out;

    k_init<<<2048, 256>>>(nt, nip, W_enc, b_enc, out);
    k_deg<<<1600, 256>>>(ei);
    k_hist<<<HB, 256>>>(fl, bl);
    k_hscan<<<1, 768>>>();
    k_assign2<<<HB, 256>>>(fl, bl);
    k_scan1<<<2 * SCAN_NB, 256>>>();
    k_scan2p<<<1, 256>>>();
    k_scan3<<<784, 256>>>();
    k_scatter_e<<<1600, 256>>>(ei);

    for (int l = 1; l < NLVL; l++) {
        k_gather<<<2048, 256>>>(l, 0);
        k_gemm<<<320, 256>>>(l, 0, W_f, b_f);
    }
    for (int l = 1; l < NLVL; l++) {
        k_gather<<<2048, 256>>>(l, 1);
        k_gemm<<<320, 256>>>(l, 1, W_b, b_b);
    }

    k_pool<<<592, 256>>>(nt, batch, out);
    k_fixup<<<1, 1024>>>(out);
}

// round 8
// speedup vs baseline: 1.7334x; 1.2360x over previous
#include <cuda_runtime.h>

#define NN 200000
#define EE 400000
#define DD 64
#define BBATCH 16
#define NLVL 12
#define SCAN_NB ((NN + 1023) / 1024)   // 196
#define HB SCAN_NB

// ---------------- device scratch ----------------
__device__ float g_f0[NN * DD];         // slot-indexed initial values
__device__ float g_fout[NN * DD];       // slot-indexed forward outputs
__device__ float g_bout[NN * DD];       // slot-indexed backward outputs
__device__ int g_indeg[NN], g_outdeg[NN];
__device__ int g_fslot[NN], g_bslot[NN];     // node -> slot
__device__ int g_fdeg[NN], g_bdeg[NN];       // slot-indexed degree
__device__ int g_feptr[NN + 1], g_beptr[NN + 1];
__device__ int g_fcur_e[NN], g_bcur_e[NN];
__device__ int g_fsrc[EE];              // fwd edges by dst-slot: fslot[src]
__device__ int2 g_bedge[EE];            // bwd edges by src-slot: (bslot[dst], fidx[dst])
__device__ int g_foff[NLVL + 1], g_boff[NLVL + 1];
__device__ int g_lhist[2 * NLVL * HB];
__device__ int g_bsum[2][SCAN_NB], g_bsum_s[2][SCAN_NB];

__device__ __forceinline__ unsigned enc_f(float f) {
    unsigned u = __float_as_uint(f);
    return (u & 0x80000000u) ? ~u : (u | 0x80000000u);
}
__device__ __forceinline__ float dec_f(unsigned u) {
    return (u & 0x80000000u) ? __uint_as_float(u & 0x7FFFFFFFu)
                             : __uint_as_float(~u);
}
#define NEGMAX (-3.402823466e38f)
#define FOUT_FLAG 0x40000000

// ---------------- K0: zero degree arrays ----------------
__global__ void k_zero() {
    int stride = gridDim.x * blockDim.x;
    for (int i = blockIdx.x * blockDim.x + threadIdx.x; i < NN; i += stride) {
        g_indeg[i] = 0;
        g_outdeg[i] = 0;
    }
}

// ---------------- K1: degrees (spread atomics) + per-block level hists ----------------
__global__ void k_deg_hist(const int* __restrict__ ei, const int* __restrict__ fl,
                           const int* __restrict__ bl) {
    __shared__ int sh[2 * NLVL];
    int t = threadIdx.x;
    if (t < 2 * NLVL) sh[t] = 0;
    __syncthreads();
    int base = blockIdx.x * 1024;
#pragma unroll
    for (int j = 0; j < 4; j++) {
        int idx = base + j * 256 + t;
        if (idx < NN) {
            atomicAdd(&sh[fl[idx]], 1);
            atomicAdd(&sh[NLVL + bl[idx]], 1);
        }
    }
    int stride = gridDim.x * blockDim.x;
    for (int i = blockIdx.x * blockDim.x + t; i < EE; i += stride) {
        atomicAdd(&g_indeg[ei[EE + i]], 1);
        atomicAdd(&g_outdeg[ei[i]], 1);
    }
    __syncthreads();
    if (t < 2 * NLVL) g_lhist[t * HB + blockIdx.x] = sh[t];
}

// ---------------- K2: scan block hists -> per-(blk,lvl) offsets + foff/boff ----------------
__global__ void k_hscan() {
    __shared__ int tot[2 * NLVL];
    __shared__ int off_s[2][NLVL + 1];
    int t = threadIdx.x;
    int wid = t >> 5, lane = t & 31;       // 24 warps
    int* row = g_lhist + wid * HB;
    int carry = 0;
#pragma unroll
    for (int r = 0; r < (HB + 31) / 32; r++) {
        int idx = r * 32 + lane;
        int v = (idx < HB) ? row[idx] : 0;
        int incl = v;
#pragma unroll
        for (int o = 1; o < 32; o <<= 1) {
            int n = __shfl_up_sync(0xffffffffu, incl, o);
            if (lane >= o) incl += n;
        }
        if (idx < HB) row[idx] = incl - v + carry;
        carry += __shfl_sync(0xffffffffu, incl, 31);
    }
    if (lane == 0) tot[wid] = carry;
    __syncthreads();
    if (wid < 2) {
        int hv = (lane < NLVL) ? tot[wid * NLVL + lane] : 0;
        int v = hv;
#pragma unroll
        for (int o = 1; o < 32; o <<= 1) {
            int n = __shfl_up_sync(0xffffffffu, v, o);
            if (lane >= o) v += n;
        }
        int excl = v - hv;
        if (lane <= NLVL) {
            off_s[wid][lane] = excl;
            (wid ? g_boff : g_foff)[lane] = excl;
        }
    }
    __syncthreads();
    int add = off_s[wid / NLVL][wid % NLVL];
#pragma unroll
    for (int r = 0; r < (HB + 31) / 32; r++) {
        int idx = r * 32 + lane;
        if (idx < HB) row[idx] += add;
    }
}

// ---------------- K3: assign slots via block-local smem counters ----------------
__global__ void k_assign2(const int* __restrict__ fl, const int* __restrict__ bl) {
    __shared__ int sc[2 * NLVL];
    int t = threadIdx.x;
    if (t < 2 * NLVL) sc[t] = g_lhist[t * HB + blockIdx.x];
    __syncthreads();
    int base = blockIdx.x * 1024;
#pragma unroll
    for (int j = 0; j < 4; j++) {
        int v = base + j * 256 + t;
        if (v < NN) {
            int s = atomicAdd(&sc[fl[v]], 1);
            g_fslot[v] = s;
            g_fdeg[s] = g_indeg[v];
            int s2 = atomicAdd(&sc[NLVL + bl[v]], 1);
            g_bslot[v] = s2;
            g_bdeg[s2] = g_outdeg[v];
        }
    }
}

// ---------------- K4: init f0 (slot-scatter) + output buffer ----------------
__global__ void k_init_f(const int* __restrict__ nt, const int* __restrict__ nip,
                         const float* __restrict__ Wenc, const float* __restrict__ benc,
                         float* __restrict__ out) {
    int stride = gridDim.x * blockDim.x;
    for (int q = blockIdx.x * blockDim.x + threadIdx.x; q < NN * DD / 4; q += stride) {
        int n = q >> 4;
        int d = (q & 15) << 2;
        float a = (float)nt[n], b = (float)nip[n];
        float4 w0 = *(const float4*)(Wenc + d);
        float4 w1 = *(const float4*)(Wenc + 64 + d);
        float4 be = *(const float4*)(benc + d);
        float4 o;
        o.x = a * w0.x + b * w1.x + be.x;
        o.y = a * w0.y + b * w1.y + be.y;
        o.z = a * w0.z + b * w1.z + be.z;
        o.w = a * w0.w + b * w1.w + be.w;
        int s = g_fslot[n];
        *(float4*)(g_f0 + (size_t)s * DD + d) = o;
        if (q < BBATCH * 2 * DD) {
            int col = q & 127;
            ((unsigned*)out)[q] = (col < 64) ? 0x00800000u : 0u;
        }
    }
}

// ---------------- K5: block-local exclusive scans of slot degrees ----------------
__global__ void k_scan1() {
    int which = blockIdx.x / SCAN_NB;   // 0 = fdeg, 1 = bdeg
    int blk = blockIdx.x % SCAN_NB;
    const int* deg = which ? g_bdeg : g_fdeg;
    int* ptr = which ? g_beptr : g_feptr;
    __shared__ int sh[256];
    int base = blk * 1024 + threadIdx.x * 4;
    int v[4];
    int s = 0;
#pragma unroll
    for (int j = 0; j < 4; j++) {
        int idx = base + j;
        v[j] = (idx < NN) ? deg[idx] : 0;
        s += v[j];
    }
    sh[threadIdx.x] = s;
    __syncthreads();
    for (int off = 1; off < 256; off <<= 1) {
        int t = 0;
        if (threadIdx.x >= off) t = sh[threadIdx.x - off];
        __syncthreads();
        sh[threadIdx.x] += t;
        __syncthreads();
    }
    int run = sh[threadIdx.x] - s;
#pragma unroll
    for (int j = 0; j < 4; j++) {
        int idx = base + j;
        if (idx < NN) ptr[idx] = run;
        run += v[j];
    }
    if (threadIdx.x == 255) g_bsum[which][blk] = sh[255];
}

// ---------------- K6: scan of block sums ----------------
__global__ void k_scan2p() {
    __shared__ int sh[256];
    int t = threadIdx.x;
#pragma unroll
    for (int w = 0; w < 2; w++) {
        int v = (t < SCAN_NB) ? g_bsum[w][t] : 0;
        sh[t] = v;
        __syncthreads();
        for (int off = 1; off < 256; off <<= 1) {
            int x = 0;
            if (t >= off) x = sh[t - off];
            __syncthreads();
            sh[t] += x;
            __syncthreads();
        }
        if (t < SCAN_NB) g_bsum_s[w][t] = sh[t] - v;
        __syncthreads();
    }
    if (t == 0) { g_feptr[NN] = EE; g_beptr[NN] = EE; }
}

// ---------------- K7: add block offsets, init edge-scatter cursors ----------------
__global__ void k_scan3() {
    int stride = gridDim.x * blockDim.x;
    for (int i = blockIdx.x * blockDim.x + threadIdx.x; i < 2 * NN; i += stride) {
        if (i < NN) {
            int v = g_feptr[i] + g_bsum_s[0][i >> 10];
            g_feptr[i] = v;
            g_fcur_e[i] = v;
        } else {
            int j = i - NN;
            int v = g_beptr[j] + g_bsum_s[1][j >> 10];
            g_beptr[j] = v;
            g_bcur_e[j] = v;
        }
    }
}

// ---------------- K8: scatter edges into slot-ordered lists ----------------
__global__ void k_scatter_e(const int* __restrict__ ei, const int* __restrict__ fl) {
    int stride = gridDim.x * blockDim.x;
    for (int i = blockIdx.x * blockDim.x + threadIdx.x; i < EE; i += stride) {
        int src = ei[i], dst = ei[EE + i];
        int fs_src = g_fslot[src];
        int fs_dst = g_fslot[dst];
        int p = atomicAdd(&g_fcur_e[fs_dst], 1);
        g_fsrc[p] = fs_src;
        int bs_src = g_bslot[src];
        int bs_dst = g_bslot[dst];
        int q = atomicAdd(&g_bcur_e[bs_src], 1);
        int fidx = fs_dst | ((fl[dst] >= 1) ? FOUT_FLAG : 0);
        g_bedge[q] = make_int2(bs_dst, fidx);
    }
}

// ---------------- fused per-level forward: gather -> GEMM -> fout ----------------
__global__ void __launch_bounds__(256) k_flevel(int level,
                                                const float* __restrict__ W,
                                                const float* __restrict__ bias) {
    __shared__ float sW[64][64];
    __shared__ float sA[64][68];
    int start = g_foff[level];
    int cnt = g_foff[level + 1] - start;
    int foff1 = g_foff[1];
    int ntiles = (cnt + 63) >> 6;

    for (int i = threadIdx.x; i < 4096; i += 256) sW[i >> 6][i & 63] = W[i];

    int tx = threadIdx.x & 15, ty = threadIdx.x >> 4;
    int n0 = tx << 2, m0 = ty << 2;
    float4 bs = *(const float4*)(bias + n0);

    int r = threadIdx.x >> 2;             // slot row in tile
    int c16 = (threadIdx.x & 3) << 4;     // 16-float chunk

    for (int tile = blockIdx.x; tile < ntiles; tile += gridDim.x) {
        int m = tile * 64 + r;
        float4 a0 = {0,0,0,0}, a1 = {0,0,0,0}, a2 = {0,0,0,0}, a3 = {0,0,0,0};
        if (m < cnt) {
            int slot = start + m;
            int e0 = __ldg(g_feptr + slot), e1 = __ldg(g_feptr + slot + 1);
            for (int e = e0; e < e1; e++) {
                int s = __ldg(g_fsrc + e);
                const float* hb = (s >= foff1 && s < start) ? g_fout : g_f0;
                const float4* b = (const float4*)(hb + (size_t)s * DD + c16);
                float4 v0 = b[0], v1 = b[1], v2 = b[2], v3 = b[3];
                a0.x += v0.x; a0.y += v0.y; a0.z += v0.z; a0.w += v0.w;
                a1.x += v1.x; a1.y += v1.y; a1.z += v1.z; a1.w += v1.w;
                a2.x += v2.x; a2.y += v2.y; a2.z += v2.z; a2.w += v2.w;
                a3.x += v3.x; a3.y += v3.y; a3.z += v3.z; a3.w += v3.w;
            }
        }
        *((float4*)&sA[r][c16 + 0]) = a0;
        *((float4*)&sA[r][c16 + 4]) = a1;
        *((float4*)&sA[r][c16 + 8]) = a2;
        *((float4*)&sA[r][c16 + 12]) = a3;
        __syncthreads();

        float c[4][4];
#pragma unroll
        for (int i = 0; i < 4; i++)
#pragma unroll
            for (int j = 0; j < 4; j++) c[i][j] = 0.f;

#pragma unroll 8
        for (int k = 0; k < 64; k++) {
            float4 b4 = *((const float4*)&sW[k][n0]);
            float x0 = sA[m0 + 0][k];
            float x1 = sA[m0 + 1][k];
            float x2 = sA[m0 + 2][k];
            float x3 = sA[m0 + 3][k];
            c[0][0] += x0 * b4.x; c[0][1] += x0 * b4.y; c[0][2] += x0 * b4.z; c[0][3] += x0 * b4.w;
            c[1][0] += x1 * b4.x; c[1][1] += x1 * b4.y; c[1][2] += x1 * b4.z; c[1][3] += x1 * b4.w;
            c[2][0] += x2 * b4.x; c[2][1] += x2 * b4.y; c[2][2] += x2 * b4.z; c[2][3] += x2 * b4.w;
            c[3][0] += x3 * b4.x; c[3][1] += x3 * b4.y; c[3][2] += x3 * b4.z; c[3][3] += x3 * b4.w;
        }

#pragma unroll
        for (int i = 0; i < 4; i++) {
            int mm = tile * 64 + m0 + i;
            if (mm < cnt) {
                int slot = start + mm;
                float dg = (float)__ldg(g_fdeg + slot);
                float4 o;
                o.x = c[i][0] + dg * bs.x;
                o.y = c[i][1] + dg * bs.y;
                o.z = c[i][2] + dg * bs.z;
                o.w = c[i][3] + dg * bs.w;
                *((float4*)(g_fout + (size_t)slot * DD + n0)) = o;
            }
        }
        __syncthreads();
    }
}

// ---------------- fused per-level backward: gather -> GEMM -> bout ----------------
__global__ void __launch_bounds__(256) k_blevel(int level,
                                                const float* __restrict__ W,
                                                const float* __restrict__ bias) {
    __shared__ float sW[64][64];
    __shared__ float sA[64][68];
    int start = g_boff[level];
    int cnt = g_boff[level + 1] - start;
    int boff1 = g_boff[1];
    int ntiles = (cnt + 63) >> 6;

    for (int i = threadIdx.x; i < 4096; i += 256) sW[i >> 6][i & 63] = W[i];

    int tx = threadIdx.x & 15, ty = threadIdx.x >> 4;
    int n0 = tx << 2, m0 = ty << 2;
    float4 bs = *(const float4*)(bias + n0);

    int r = threadIdx.x >> 2;
    int c16 = (threadIdx.x & 3) << 4;

    for (int tile = blockIdx.x; tile < ntiles; tile += gridDim.x) {
        int m = tile * 64 + r;
        float4 a0 = {0,0,0,0}, a1 = {0,0,0,0}, a2 = {0,0,0,0}, a3 = {0,0,0,0};
        if (m < cnt) {
            int slot = start + m;
            int e0 = __ldg(g_beptr + slot), e1 = __ldg(g_beptr + slot + 1);
            for (int e = e0; e < e1; e++) {
                int2 ee = __ldg(g_bedge + e);
                int s = ee.x;
                const float* base;
                if (s >= boff1 && s < start) {
                    base = g_bout + (size_t)s * DD + c16;
                } else {
                    int f = ee.y;
                    const float* hb = (f & FOUT_FLAG) ? g_fout : g_f0;
                    base = hb + (size_t)(f & (FOUT_FLAG - 1)) * DD + c16;
                }
                const float4* b = (const float4*)base;
                float4 v0 = b[0], v1 = b[1], v2 = b[2], v3 = b[3];
                a0.x += v0.x; a0.y += v0.y; a0.z += v0.z; a0.w += v0.w;
                a1.x += v1.x; a1.y += v1.y; a1.z += v1.z; a1.w += v1.w;
                a2.x += v2.x; a2.y += v2.y; a2.z += v2.z; a2.w += v2.w;
                a3.x += v3.x; a3.y += v3.y; a3.z += v3.z; a3.w += v3.w;
            }
        }
        *((float4*)&sA[r][c16 + 0]) = a0;
        *((float4*)&sA[r][c16 + 4]) = a1;
        *((float4*)&sA[r][c16 + 8]) = a2;
        *((float4*)&sA[r][c16 + 12]) = a3;
        __syncthreads();

        float c[4][4];
#pragma unroll
        for (int i = 0; i < 4; i++)
#pragma unroll
            for (int j = 0; j < 4; j++) c[i][j] = 0.f;

#pragma unroll 8
        for (int k = 0; k < 64; k++) {
            float4 b4 = *((const float4*)&sW[k][n0]);
            float x0 = sA[m0 + 0][k];
            float x1 = sA[m0 + 1][k];
            float x2 = sA[m0 + 2][k];
            float x3 = sA[m0 + 3][k];
            c[0][0] += x0 * b4.x; c[0][1] += x0 * b4.y; c[0][2] += x0 * b4.z; c[0][3] += x0 * b4.w;
            c[1][0] += x1 * b4.x; c[1][1] += x1 * b4.y; c[1][2] += x1 * b4.z; c[1][3] += x1 * b4.w;
            c[2][0] += x2 * b4.x; c[2][1] += x2 * b4.y; c[2][2] += x2 * b4.z; c[2][3] += x2 * b4.w;
            c[3][0] += x3 * b4.x; c[3][1] += x3 * b4.y; c[3][2] += x3 * b4.z; c[3][3] += x3 * b4.w;
        }

#pragma unroll
        for (int i = 0; i < 4; i++) {
            int mm = tile * 64 + m0 + i;
            if (mm < cnt) {
                int slot = start + mm;
                float dg = (float)__ldg(g_bdeg + slot);
                float4 o;
                o.x = c[i][0] + dg * bs.x;
                o.y = c[i][1] + dg * bs.y;
                o.z = c[i][2] + dg * bs.z;
                o.w = c[i][3] + dg * bs.w;
                *((float4*)(g_bout + (size_t)slot * DD + n0)) = o;
            }
        }
        __syncthreads();
    }
}

// ---------------- readout ----------------
__device__ __forceinline__ void pool_flush(int cb, float2 mx, float2 sm, int lane,
                                           float* out) {
    int d = 2 * lane;
    unsigned* uo = (unsigned*)out;
    atomicMax(&uo[cb * 128 + d], enc_f(mx.x));
    atomicMax(&uo[cb * 128 + d + 1], enc_f(mx.y));
    atomicAdd(&out[cb * 128 + 64 + d], sm.x);
    atomicAdd(&out[cb * 128 + 64 + d + 1], sm.y);
}

__global__ void k_pool(const int* __restrict__ nt, const int* __restrict__ batch,
                       const int* __restrict__ fl, const int* __restrict__ bl,
                       float* __restrict__ out) {
    int chunk = (NN + gridDim.x - 1) / gridDim.x;
    int s = blockIdx.x * chunk;
    int e = min(NN, s + chunk);
    if (s >= e) return;
    int warp = threadIdx.x >> 5, lane = threadIdx.x & 31;
    int nw = blockDim.x >> 5;
    int len = e - s;
    int wchunk = (len + nw - 1) / nw;
    int ws = s + warp * wchunk;
    int we = min(e, ws + wchunk);
    float2 mx = make_float2(NEGMAX, NEGMAX);
    float2 sm = make_float2(0.f, 0.f);
    int cb = (ws < we) ? batch[ws] : -1;
    for (int n = ws; n < we; n++) {
        int bb = batch[n];
        if (bb != cb) {
            pool_flush(cb, mx, sm, lane, out);
            mx = make_float2(NEGMAX, NEGMAX);
            sm = make_float2(0.f, 0.f);
            cb = bb;
        }
        if (nt[n] == 1) {
            const float* base;
            if (bl[n] >= 1) {
                base = g_bout + (size_t)g_bslot[n] * DD;
            } else {
                const float* hb = (fl[n] >= 1) ? g_fout : g_f0;
                base = hb + (size_t)g_fslot[n] * DD;
            }
            float2 v = *((const float2*)base + lane);
            mx.x = fmaxf(mx.x, v.x);
            mx.y = fmaxf(mx.y, v.y);
            sm.x += v.x;
            sm.y += v.y;
        }
    }
    if (cb >= 0) pool_flush(cb, mx, sm, lane, out);
}

__global__ void k_fixup(float* __restrict__ out) {
    int i = threadIdx.x;           // 1024 = B*64
    int b = i >> 6, d = i & 63;
    int pos = b * 128 + d;
    unsigned u = ((unsigned*)out)[pos];
    out[pos] = dec_f(u);
}

// ---------------- launch ----------------
extern "C" void kernel_launch(void* const* d_in, const int* in_sizes, int n_in,
                              void* d_out, int out_size) {
    const int* nt    = (const int*)d_in[0];
    const int* nip   = (const int*)d_in[1];
    const int* ei    = (const int*)d_in[2];
    const int* fl    = (const int*)d_in[3];
    const int* bl    = (const int*)d_in[4];
    const int* batch = (const int*)d_in[5];
    const float* W_enc = (const float*)d_in[6];
    const float* b_enc = (const float*)d_in[7];
    const float* W_f   = (const float*)d_in[8];
    const float* b_f   = (const float*)d_in[9];
    const float* W_b   = (const float*)d_in[10];
    const float* b_b   = (const float*)d_in[11];
    float* out = (float*)d_out;

    k_zero<<<196, 256>>>();
    k_deg_hist<<<HB, 256>>>(ei, fl, bl);
    k_hscan<<<1, 768>>>();
    k_assign2<<<HB, 256>>>(fl, bl);
    k_init_f<<<2048, 256>>>(nt, nip, W_enc, b_enc, out);
    k_scan1<<<2 * SCAN_NB, 256>>>();
    k_scan2p<<<1, 256>>>();
    k_scan3<<<784, 256>>>();
    k_scatter_e<<<1600, 256>>>(ei, fl);

    for (int l = 1; l < NLVL; l++) k_flevel<<<320, 256>>>(l, W_f, b_f);
    for (int l = 1; l < NLVL; l++) k_blevel<<<320, 256>>>(l, W_b, b_b);

    k_pool<<<592, 256>>>(nt, batch, fl, bl, out);
    k_fixup<<<1, 1024>>>(out);
}

// round 10
// speedup vs baseline: 1.7890x; 1.0321x over previous
#include <cuda_runtime.h>

#define NN 200000
#define EE 400000
#define DD 64
#define BBATCH 16
#define NLVL 12
#define SCAN_NB ((NN + 1023) / 1024)   // 196
#define HB SCAN_NB
#define SLOT_MASK 0xFFFFF
#define FOUT_FLAG 0x40000000

// ---------------- device scratch ----------------
__device__ float g_fout[NN * DD];       // slot-indexed forward outputs
__device__ float g_bout[NN * DD];       // slot-indexed backward outputs
__device__ float g_tab[9 * DD];         // 9 distinct f0 rows (nt*3+nip)
__device__ int g_indeg[NN], g_outdeg[NN];
__device__ int g_fslot[NN], g_bslot[NN];     // node -> slot (fslot packs type<<20)
__device__ int g_fdeg[NN], g_bdeg[NN];       // slot-indexed degree
__device__ int g_feptr[NN + 1], g_beptr[NN + 1];
__device__ int g_fcur_e[NN], g_bcur_e[NN];
__device__ int g_fsrc[EE];              // fwd edges by dst-slot: packed fslot[src]
__device__ int2 g_bedge[EE];            // bwd edges by src-slot: (bslot[dst], fidx[dst])
__device__ int g_foff[NLVL + 1], g_boff[NLVL + 1];
__device__ int g_lhist[2 * NLVL * HB];
__device__ int g_bsum[2][SCAN_NB], g_bsum_s[2][SCAN_NB];

__device__ __forceinline__ unsigned enc_f(float f) {
    unsigned u = __float_as_uint(f);
    return (u & 0x80000000u) ? ~u : (u | 0x80000000u);
}
__device__ __forceinline__ float dec_f(unsigned u) {
    return (u & 0x80000000u) ? __uint_as_float(u & 0x7FFFFFFFu)
                             : __uint_as_float(~u);
}
#define NEGMAX (-3.402823466e38f)

// ---------------- K0: zero degree arrays + init output buffer ----------------
__global__ void k_zero(float* __restrict__ out) {
    int stride = gridDim.x * blockDim.x;
    for (int i = blockIdx.x * blockDim.x + threadIdx.x; i < NN; i += stride) {
        g_indeg[i] = 0;
        g_outdeg[i] = 0;
        if (i < BBATCH * 2 * DD) {
            int col = i & 127;
            ((unsigned*)out)[i] = (col < 64) ? 0x00800000u : 0u;
        }
    }
}

// ---------------- K1: degrees (spread atomics) + per-block level hists ----------------
__global__ void k_deg_hist(const int* __restrict__ ei, const int* __restrict__ fl,
                           const int* __restrict__ bl) {
    __shared__ int sh[2 * NLVL];
    int t = threadIdx.x;
    if (t < 2 * NLVL) sh[t] = 0;
    __syncthreads();
    int base = blockIdx.x * 1024;
#pragma unroll
    for (int j = 0; j < 4; j++) {
        int idx = base + j * 256 + t;
        if (idx < NN) {
            atomicAdd(&sh[fl[idx]], 1);
            atomicAdd(&sh[NLVL + bl[idx]], 1);
        }
    }
    int stride = gridDim.x * blockDim.x;
    for (int i = blockIdx.x * blockDim.x + t; i < EE; i += stride) {
        atomicAdd(&g_indeg[ei[EE + i]], 1);
        atomicAdd(&g_outdeg[ei[i]], 1);
    }
    __syncthreads();
    if (t < 2 * NLVL) g_lhist[t * HB + blockIdx.x] = sh[t];
}

// ---------------- K2: scan block hists -> per-(blk,lvl) offsets + foff/boff ----------------
__global__ void k_hscan() {
    __shared__ int tot[2 * NLVL];
    __shared__ int off_s[2][NLVL + 1];
    int t = threadIdx.x;
    int wid = t >> 5, lane = t & 31;       // 24 warps
    int* row = g_lhist + wid * HB;
    int carry = 0;
#pragma unroll
    for (int r = 0; r < (HB + 31) / 32; r++) {
        int idx = r * 32 + lane;
        int v = (idx < HB) ? row[idx] : 0;
        int incl = v;
#pragma unroll
        for (int o = 1; o < 32; o <<= 1) {
            int n = __shfl_up_sync(0xffffffffu, incl, o);
            if (lane >= o) incl += n;
        }
        if (idx < HB) row[idx] = incl - v + carry;
        carry += __shfl_sync(0xffffffffu, incl, 31);
    }
    if (lane == 0) tot[wid] = carry;
    __syncthreads();
    if (wid < 2) {
        int hv = (lane < NLVL) ? tot[wid * NLVL + lane] : 0;
        int v = hv;
#pragma unroll
        for (int o = 1; o < 32; o <<= 1) {
            int n = __shfl_up_sync(0xffffffffu, v, o);
            if (lane >= o) v += n;
        }
        int excl = v - hv;
        if (lane <= NLVL) {
            off_s[wid][lane] = excl;
            (wid ? g_boff : g_foff)[lane] = excl;
        }
    }
    __syncthreads();
    int add = off_s[wid / NLVL][wid % NLVL];
#pragma unroll
    for (int r = 0; r < (HB + 31) / 32; r++) {
        int idx = r * 32 + lane;
        if (idx < HB) row[idx] += add;
    }
}

// ---------------- K3: assign slots (pack nt/nip type into fslot) ----------------
__global__ void k_assign2(const int* __restrict__ fl, const int* __restrict__ bl,
                          const int* __restrict__ nt, const int* __restrict__ nip) {
    __shared__ int sc[2 * NLVL];
    int t = threadIdx.x;
    if (t < 2 * NLVL) sc[t] = g_lhist[t * HB + blockIdx.x];
    __syncthreads();
    int base = blockIdx.x * 1024;
#pragma unroll
    for (int j = 0; j < 4; j++) {
        int v = base + j * 256 + t;
        if (v < NN) {
            int type = nt[v] * 3 + nip[v];
            int s = atomicAdd(&sc[fl[v]], 1);
            g_fslot[v] = s | (type << 20);
            g_fdeg[s] = g_indeg[v];
            int s2 = atomicAdd(&sc[NLVL + bl[v]], 1);
            g_bslot[v] = s2;
            g_bdeg[s2] = g_outdeg[v];
        }
    }
}

// ---------------- K4: block-local exclusive scans of slot degrees ----------------
__global__ void k_scan1() {
    int which = blockIdx.x / SCAN_NB;   // 0 = fdeg, 1 = bdeg
    int blk = blockIdx.x % SCAN_NB;
    const int* deg = which ? g_bdeg : g_fdeg;
    int* ptr = which ? g_beptr : g_feptr;
    __shared__ int sh[256];
    int base = blk * 1024 + threadIdx.x * 4;
    int v[4];
    int s = 0;
#pragma unroll
    for (int j = 0; j < 4; j++) {
        int idx = base + j;
        v[j] = (idx < NN) ? deg[idx] : 0;
        s += v[j];
    }
    sh[threadIdx.x] = s;
    __syncthreads();
    for (int off = 1; off < 256; off <<= 1) {
        int t = 0;
        if (threadIdx.x >= off) t = sh[threadIdx.x - off];
        __syncthreads();
        sh[threadIdx.x] += t;
        __syncthreads();
    }
    int run = sh[threadIdx.x] - s;
#pragma unroll
    for (int j = 0; j < 4; j++) {
        int idx = base + j;
        if (idx < NN) ptr[idx] = run;
        run += v[j];
    }
    if (threadIdx.x == 255) g_bsum[which][blk] = sh[255];
}

// ---------------- K5: scan of block sums + build f0 table ----------------
__global__ void k_scan2p(const float* __restrict__ Wenc, const float* __restrict__ benc) {
    __shared__ int sh[256];
    int t = threadIdx.x;
#pragma unroll
    for (int w = 0; w < 2; w++) {
        int v = (t < SCAN_NB) ? g_bsum[w][t] : 0;
        sh[t] = v;
        __syncthreads();
        for (int off = 1; off < 256; off <<= 1) {
            int x = 0;
            if (t >= off) x = sh[t - off];
            __syncthreads();
            sh[t] += x;
            __syncthreads();
        }
        if (t < SCAN_NB) g_bsum_s[w][t] = sh[t] - v;
        __syncthreads();
    }
    if (t == 0) { g_feptr[NN] = EE; g_beptr[NN] = EE; }
    // 9-row f0 table: tab[type][d] = (type/3)*Wenc[d] + (type%3)*Wenc[64+d] + benc[d]
    for (int i = t; i < 9 * DD; i += 256) {
        int ty = i >> 6, d = i & 63;
        g_tab[i] = (float)(ty / 3) * Wenc[d] + (float)(ty % 3) * Wenc[64 + d] + benc[d];
    }
}

// ---------------- K6: add block offsets, init edge-scatter cursors ----------------
__global__ void k_scan3() {
    int stride = gridDim.x * blockDim.x;
    for (int i = blockIdx.x * blockDim.x + threadIdx.x; i < 2 * NN; i += stride) {
        if (i < NN) {
            int v = g_feptr[i] + g_bsum_s[0][i >> 10];
            g_feptr[i] = v;
            g_fcur_e[i] = v;
        } else {
            int j = i - NN;
            int v = g_beptr[j] + g_bsum_s[1][j >> 10];
            g_beptr[j] = v;
            g_bcur_e[j] = v;
        }
    }
}

// ---------------- K7: scatter edges into slot-ordered lists ----------------
__global__ void k_scatter_e(const int* __restrict__ ei, const int* __restrict__ fl) {
    int stride = gridDim.x * blockDim.x;
    for (int i = blockIdx.x * blockDim.x + threadIdx.x; i < EE; i += stride) {
        int src = ei[i], dst = ei[EE + i];
        int fp_src = g_fslot[src];             // packed slot | type<<20
        int fp_dst = g_fslot[dst];
        int p = atomicAdd(&g_fcur_e[fp_dst & SLOT_MASK], 1);
        g_fsrc[p] = fp_src;
        int bs_src = g_bslot[src];
        int bs_dst = g_bslot[dst];
        int q = atomicAdd(&g_bcur_e[bs_src], 1);
        int fidx = fp_dst | ((fl[dst] >= 1) ? FOUT_FLAG : 0);
        g_bedge[q] = make_int2(bs_dst, fidx);
    }
}

// ---------------- fused per-level forward: gather -> GEMM -> fout ----------------
__global__ void __launch_bounds__(256) k_flevel(int level,
                                                const float* __restrict__ W,
                                                const float* __restrict__ bias) {
    __shared__ float sW[64][64];
    __shared__ float sA[64][68];
    int start = g_foff[level];
    int cnt = g_foff[level + 1] - start;
    int foff1 = g_foff[1];
    int ntiles = (cnt + 63) >> 6;

    for (int i = threadIdx.x; i < 4096; i += 256) sW[i >> 6][i & 63] = W[i];

    int tx = threadIdx.x & 15, ty = threadIdx.x >> 4;
    int n0 = tx << 2, m0 = ty << 2;
    float4 bs = *(const float4*)(bias + n0);

    int r = threadIdx.x >> 2;             // slot row in tile
    int c16 = (threadIdx.x & 3) << 4;     // 16-float chunk

    for (int tile = blockIdx.x; tile < ntiles; tile += gridDim.x) {
        int m = tile * 64 + r;
        float4 a0 = {0,0,0,0}, a1 = {0,0,0,0}, a2 = {0,0,0,0}, a3 = {0,0,0,0};
        if (m < cnt) {
            int slot = start + m;
            int e0 = __ldg(g_feptr + slot), e1 = __ldg(g_feptr + slot + 1);
            for (int e = e0; e < e1; e++) {
                int v = __ldg(g_fsrc + e);
                int s = v & SLOT_MASK;
                const float* hb = (s >= foff1 && s < start)
                    ? g_fout + (size_t)s * DD
                    : g_tab + ((v >> 20) & 0xF) * DD;
                const float4* b = (const float4*)(hb + c16);
                float4 v0 = b[0], v1 = b[1], v2 = b[2], v3 = b[3];
                a0.x += v0.x; a0.y += v0.y; a0.z += v0.z; a0.w += v0.w;
                a1.x += v1.x; a1.y += v1.y; a1.z += v1.z; a1.w += v1.w;
                a2.x += v2.x; a2.y += v2.y; a2.z += v2.z; a2.w += v2.w;
                a3.x += v3.x; a3.y += v3.y; a3.z += v3.z; a3.w += v3.w;
            }
        }
        *((float4*)&sA[r][c16 + 0]) = a0;
        *((float4*)&sA[r][c16 + 4]) = a1;
        *((float4*)&sA[r][c16 + 8]) = a2;
        *((float4*)&sA[r][c16 + 12]) = a3;
        __syncthreads();

        float c[4][4];
#pragma unroll
        for (int i = 0; i < 4; i++)
#pragma unroll
            for (int j = 0; j < 4; j++) c[i][j] = 0.f;

#pragma unroll 8
        for (int k = 0; k < 64; k++) {
            float4 b4 = *((const float4*)&sW[k][n0]);
            float x0 = sA[m0 + 0][k];
            float x1 = sA[m0 + 1][k];
            float x2 = sA[m0 + 2][k];
            float x3 = sA[m0 + 3][k];
            c[0][0] += x0 * b4.x; c[0][1] += x0 * b4.y; c[0][2] += x0 * b4.z; c[0][3] += x0 * b4.w;
            c[1][0] += x1 * b4.x; c[1][1] += x1 * b4.y; c[1][2] += x1 * b4.z; c[1][3] += x1 * b4.w;
            c[2][0] += x2 * b4.x; c[2][1] += x2 * b4.y; c[2][2] += x2 * b4.z; c[2][3] += x2 * b4.w;
            c[3][0] += x3 * b4.x; c[3][1] += x3 * b4.y; c[3][2] += x3 * b4.z; c[3][3] += x3 * b4.w;
        }

#pragma unroll
        for (int i = 0; i < 4; i++) {
            int mm = tile * 64 + m0 + i;
            if (mm < cnt) {
                int slot = start + mm;
                float dg = (float)__ldg(g_fdeg + slot);
                float4 o;
                o.x = c[i][0] + dg * bs.x;
                o.y = c[i][1] + dg * bs.y;
                o.z = c[i][2] + dg * bs.z;
                o.w = c[i][3] + dg * bs.w;
                *((float4*)(g_fout + (size_t)slot * DD + n0)) = o;
            }
        }
        __syncthreads();
    }
}

// ---------------- fused per-level backward: gather -> GEMM -> bout ----------------
__global__ void __launch_bounds__(256) k_blevel(int level,
                                                const float* __restrict__ W,
                                                const float* __restrict__ bias) {
    __shared__ float sW[64][64];
    __shared__ float sA[64][68];
    int start = g_boff[level];
    int cnt = g_boff[level + 1] - start;
    int boff1 = g_boff[1];
    int ntiles = (cnt + 63) >> 6;

    for (int i = threadIdx.x; i < 4096; i += 256) sW[i >> 6][i & 63] = W[i];

    int tx = threadIdx.x & 15, ty = threadIdx.x >> 4;
    int n0 = tx << 2, m0 = ty << 2;
    float4 bs = *(const float4*)(bias + n0);

    int r = threadIdx.x >> 2;
    int c16 = (threadIdx.x & 3) << 4;

    for (int tile = blockIdx.x; tile < ntiles; tile += gridDim.x) {
        int m = tile * 64 + r;
        float4 a0 = {0,0,0,0}, a1 = {0,0,0,0}, a2 = {0,0,0,0}, a3 = {0,0,0,0};
        if (m < cnt) {
            int slot = start + m;
            int e0 = __ldg(g_beptr + slot), e1 = __ldg(g_beptr + slot + 1);
            for (int e = e0; e < e1; e++) {
                int2 ee = __ldg(g_bedge + e);
                int s = ee.x;
                const float* hb;
                if (s >= boff1 && s < start) {
                    hb = g_bout + (size_t)s * DD;
                } else {
                    int f = ee.y;
                    hb = (f & FOUT_FLAG)
                        ? g_fout + (size_t)(f & SLOT_MASK) * DD
                        : g_tab + ((f >> 20) & 0xF) * DD;
                }
                const float4* b = (const float4*)(hb + c16);
                float4 v0 = b[0], v1 = b[1], v2 = b[2], v3 = b[3];
                a0.x += v0.x; a0.y += v0.y; a0.z += v0.z; a0.w += v0.w;
                a1.x += v1.x; a1.y += v1.y; a1.z += v1.z; a1.w += v1.w;
                a2.x += v2.x; a2.y += v2.y; a2.z += v2.z; a2.w += v2.w;
                a3.x += v3.x; a3.y += v3.y; a3.z += v3.z; a3.w += v3.w;
            }
        }
        *((float4*)&sA[r][c16 + 0]) = a0;
        *((float4*)&sA[r][c16 + 4]) = a1;
        *((float4*)&sA[r][c16 + 8]) = a2;
        *((float4*)&sA[r][c16 + 12]) = a3;
        __syncthreads();

        float c[4][4];
#pragma unroll
        for (int i = 0; i < 4; i++)
#pragma unroll
            for (int j = 0; j < 4; j++) c[i][j] = 0.f;

#pragma unroll 8
        for (int k = 0; k < 64; k++) {
            float4 b4 = *((const float4*)&sW[k][n0]);
            float x0 = sA[m0 + 0][k];
            float x1 = sA[m0 + 1][k];
            float x2 = sA[m0 + 2][k];
            float x3 = sA[m0 + 3][k];
            c[0][0] += x0 * b4.x; c[0][1] += x0 * b4.y; c[0][2] += x0 * b4.z; c[0][3] += x0 * b4.w;
            c[1][0] += x1 * b4.x; c[1][1] += x1 * b4.y; c[1][2] += x1 * b4.z; c[1][3] += x1 * b4.w;
            c[2][0] += x2 * b4.x; c[2][1] += x2 * b4.y; c[2][2] += x2 * b4.z; c[2][3] += x2 * b4.w;
            c[3][0] += x3 * b4.x; c[3][1] += x3 * b4.y; c[3][2] += x3 * b4.z; c[3][3] += x3 * b4.w;
        }

#pragma unroll
        for (int i = 0; i < 4; i++) {
            int mm = tile * 64 + m0 + i;
            if (mm < cnt) {
                int slot = start + mm;
                float dg = (float)__ldg(g_bdeg + slot);
                float4 o;
                o.x = c[i][0] + dg * bs.x;
                o.y = c[i][1] + dg * bs.y;
                o.z = c[i][2] + dg * bs.z;
                o.w = c[i][3] + dg * bs.w;
                *((float4*)(g_bout + (size_t)slot * DD + n0)) = o;
            }
        }
        __syncthreads();
    }
}

// ---------------- readout ----------------
__device__ __forceinline__ void pool_flush(int cb, float2 mx, float2 sm, int lane,
                                           float* out) {
    int d = 2 * lane;
    unsigned* uo = (unsigned*)out;
    atomicMax(&uo[cb * 128 + d], enc_f(mx.x));
    atomicMax(&uo[cb * 128 + d + 1], enc_f(mx.y));
    atomicAdd(&out[cb * 128 + 64 + d], sm.x);
    atomicAdd(&out[cb * 128 + 64 + d + 1], sm.y);
}

__global__ void k_pool(const int* __restrict__ nt, const int* __restrict__ batch,
                       const int* __restrict__ fl, const int* __restrict__ bl,
                       float* __restrict__ out) {
    int chunk = (NN + gridDim.x - 1) / gridDim.x;
    int s = blockIdx.x * chunk;
    int e = min(NN, s + chunk);
    if (s >= e) return;
    int warp = threadIdx.x >> 5, lane = threadIdx.x & 31;
    int nw = blockDim.x >> 5;
    int len = e - s;
    int wchunk = (len + nw - 1) / nw;
    int ws = s + warp * wchunk;
    int we = min(e, ws + wchunk);
    float2 mx = make_float2(NEGMAX, NEGMAX);
    float2 sm = make_float2(0.f, 0.f);
    int cb = (ws < we) ? batch[ws] : -1;
    for (int n = ws; n < we; n++) {
        int bb = batch[n];
        if (bb != cb) {
            pool_flush(cb, mx, sm, lane, out);
            mx = make_float2(NEGMAX, NEGMAX);
            sm = make_float2(0.f, 0.f);
            cb = bb;
        }
        if (nt[n] == 1) {
            const float* base;
            if (bl[n] >= 1) {
                base = g_bout + (size_t)g_bslot[n] * DD;
            } else {
                int fp = g_fslot[n];
                base = (fl[n] >= 1)
                    ? g_fout + (size_t)(fp & SLOT_MASK) * DD
                    : g_tab + ((fp >> 20) & 0xF) * DD;
            }
            float2 v = *((const float2*)base + lane);
            mx.x = fmaxf(mx.x, v.x);
            mx.y = fmaxf(mx.y, v.y);
            sm.x += v.x;
            sm.y += v.y;
        }
    }
    if (cb >= 0) pool_flush(cb, mx, sm, lane, out);
}

__global__ void k_fixup(float* __restrict__ out) {
    int i = threadIdx.x;           // 1024 = B*64
    int b = i >> 6, d = i & 63;
    int pos = b * 128 + d;
    unsigned u = ((unsigned*)out)[pos];
    out[pos] = dec_f(u);
}

// ---------------- launch ----------------
extern "C" void kernel_launch(void* const* d_in, const int* in_sizes, int n_in,
                              void* d_out, int out_size) {
    const int* nt    = (const int*)d_in[0];
    const int* nip   = (const int*)d_in[1];
    const int* ei    = (const int*)d_in[2];
    const int* fl    = (const int*)d_in[3];
    const int* bl    = (const int*)d_in[4];
    const int* batch = (const int*)d_in[5];
    const float* W_enc = (const float*)d_in[6];
    const float* b_enc = (const float*)d_in[7];
    const float* W_f   = (const float*)d_in[8];
    const float* b_f   = (const float*)d_in[9];
    const float* W_b   = (const float*)d_in[10];
    const float* b_b   = (const float*)d_in[11];
    float* out = (float*)d_out;

    k_zero<<<196, 256>>>(out);
    k_deg_hist<<<HB, 256>>>(ei, fl, bl);
    k_hscan<<<1, 768>>>();
    k_assign2<<<HB, 256>>>(fl, bl, nt, nip);
    k_scan1<<<2 * SCAN_NB, 256>>>();
    k_scan2p<<<1, 256>>>(W_enc, b_enc);
    k_scan3<<<784, 256>>>();
    k_scatter_e<<<1600, 256>>>(ei, fl);

    for (int l = 1; l < NLVL; l++) k_flevel<<<320, 256>>>(l, W_f, b_f);
    for (int l = 1; l < NLVL; l++) k_blevel<<<320, 256>>>(l, W_b, b_b);

    k_pool<<<592, 256>>>(nt, batch, fl, bl, out);
    k_fixup<<<1, 1024>>>(out);
}

// round 11
// speedup vs baseline: 1.9102x; 1.0677x over previous
#include <cuda_runtime.h>

#define NN 200000
#define EE 400000
#define DD 64
#define BBATCH 16
#define NLVL 12
#define SCAN_NB ((NN + 1023) / 1024)   // 196 (degree scans, 1024/block)
#define NB2 784                        // node-chunk blocks (256 nodes/block)
#define SLOT_MASK 0xFFFFF
#define FOUT_FLAG 0x40000000

// ---------------- device scratch ----------------
__device__ float g_fout[NN * DD];       // slot-indexed forward outputs
__device__ float g_bout[NN * DD];       // slot-indexed backward outputs
__device__ float g_tab[9 * DD];         // 9 distinct f0 rows (nt*3+nip)
__device__ int g_indeg[NN], g_outdeg[NN];
__device__ int g_fslot[NN], g_bslot[NN];     // node -> slot (fslot packs type<<20)
__device__ int g_fdeg[NN], g_bdeg[NN];       // slot-indexed degree
__device__ int g_feptr[NN + 1], g_beptr[NN + 1];
__device__ int g_fcur_e[NN], g_bcur_e[NN];
__device__ int g_fsrc[EE];              // fwd edges by dst-slot: packed fslot[src]
__device__ int2 g_bedge[EE];            // bwd edges by src-slot: (bslot[dst], fidx[dst])
__device__ int g_foff[NLVL + 1], g_boff[NLVL + 1];
__device__ int g_lhist[2 * NLVL * NB2];
__device__ int g_bsum[2][SCAN_NB], g_bsum_s[2][SCAN_NB];

__device__ __forceinline__ unsigned enc_f(float f) {
    unsigned u = __float_as_uint(f);
    return (u & 0x80000000u) ? ~u : (u | 0x80000000u);
}
__device__ __forceinline__ float dec_f(unsigned u) {
    return (u & 0x80000000u) ? __uint_as_float(u & 0x7FFFFFFFu)
                             : __uint_as_float(~u);
}
#define NEGMAX (-3.402823466e38f)

// ---------------- K0: zero degree arrays + init output buffer ----------------
__global__ void k_zero(float* __restrict__ out) {
    int stride = gridDim.x * blockDim.x;
    for (int i = blockIdx.x * blockDim.x + threadIdx.x; i < NN; i += stride) {
        g_indeg[i] = 0;
        g_outdeg[i] = 0;
        if (i < BBATCH * 2 * DD) {
            int col = i & 127;
            ((unsigned*)out)[i] = (col < 64) ? 0x00800000u : 0u;
        }
    }
}

// ---------------- K1: node level hists (pre-sync) + edge degrees (post-sync) ----------------
__global__ void k_deg_hist(const int* __restrict__ ei, const int* __restrict__ fl,
                           const int* __restrict__ bl) {
    __shared__ int sh[2 * NLVL];
    int t = threadIdx.x;
    if (t < 2 * NLVL) sh[t] = 0;
    __syncthreads();
    int idx = blockIdx.x * 256 + t;          // one node per thread
    if (idx < NN) {
        atomicAdd(&sh[fl[idx]], 1);
        atomicAdd(&sh[NLVL + bl[idx]], 1);
    }
    cudaGridDependencySynchronize();         // wait k_zero (g_indeg/outdeg ready)
    int stride = gridDim.x * blockDim.x;
    for (int i = blockIdx.x * blockDim.x + t; i < EE; i += stride) {
        atomicAdd(&g_indeg[ei[EE + i]], 1);
        atomicAdd(&g_outdeg[ei[i]], 1);
    }
    __syncthreads();
    if (t < 2 * NLVL) g_lhist[t * NB2 + blockIdx.x] = sh[t];
}

// ---------------- K2: scan block hists -> per-(blk,lvl) offsets + foff/boff ----------------
__global__ void k_hscan() {
    __shared__ int tot[2 * NLVL];
    __shared__ int off_s[2][NLVL + 1];
    int t = threadIdx.x;
    int wid = t >> 5, lane = t & 31;       // 24 warps
    cudaGridDependencySynchronize();
    int* row = g_lhist + wid * NB2;
    int carry = 0;
#pragma unroll
    for (int r = 0; r < (NB2 + 31) / 32; r++) {
        int idx = r * 32 + lane;
        int v = (idx < NB2) ? row[idx] : 0;
        int incl = v;
#pragma unroll
        for (int o = 1; o < 32; o <<= 1) {
            int n = __shfl_up_sync(0xffffffffu, incl, o);
            if (lane >= o) incl += n;
        }
        if (idx < NB2) row[idx] = incl - v + carry;
        carry += __shfl_sync(0xffffffffu, incl, 31);
    }
    if (lane == 0) tot[wid] = carry;
    __syncthreads();
    if (wid < 2) {
        int hv = (lane < NLVL) ? tot[wid * NLVL + lane] : 0;
        int v = hv;
#pragma unroll
        for (int o = 1; o < 32; o <<= 1) {
            int n = __shfl_up_sync(0xffffffffu, v, o);
            if (lane >= o) v += n;
        }
        int excl = v - hv;
        if (lane <= NLVL) {
            off_s[wid][lane] = excl;
            (wid ? g_boff : g_foff)[lane] = excl;
        }
    }
    __syncthreads();
    int add = off_s[wid / NLVL][wid % NLVL];
#pragma unroll
    for (int r = 0; r < (NB2 + 31) / 32; r++) {
        int idx = r * 32 + lane;
        if (idx < NB2) row[idx] += add;
    }
}

// ---------------- K3: assign slots (pack nt/nip type into fslot) ----------------
__global__ void k_assign2(const int* __restrict__ fl, const int* __restrict__ bl,
                          const int* __restrict__ nt, const int* __restrict__ nip) {
    __shared__ int sc[2 * NLVL];
    int t = threadIdx.x;
    int v = blockIdx.x * 256 + t;            // one node per thread
    // pre-sync: read inputs only
    int type = 0, flv = 0, blv = 0;
    if (v < NN) {
        type = nt[v] * 3 + nip[v];
        flv = fl[v];
        blv = bl[v];
    }
    cudaGridDependencySynchronize();
    if (t < 2 * NLVL) sc[t] = g_lhist[t * NB2 + blockIdx.x];
    __syncthreads();
    if (v < NN) {
        int s = atomicAdd(&sc[flv], 1);
        g_fslot[v] = s | (type << 20);
        g_fdeg[s] = g_indeg[v];
        int s2 = atomicAdd(&sc[NLVL + blv], 1);
        g_bslot[v] = s2;
        g_bdeg[s2] = g_outdeg[v];
    }
}

// ---------------- K4: block-local exclusive scans of slot degrees ----------------
__global__ void k_scan1() {
    int which = blockIdx.x / SCAN_NB;   // 0 = fdeg, 1 = bdeg
    int blk = blockIdx.x % SCAN_NB;
    const int* deg = which ? g_bdeg : g_fdeg;
    int* ptr = which ? g_beptr : g_feptr;
    __shared__ int sh[256];
    int base = blk * 1024 + threadIdx.x * 4;
    cudaGridDependencySynchronize();
    int v[4];
    int s = 0;
#pragma unroll
    for (int j = 0; j < 4; j++) {
        int idx = base + j;
        v[j] = (idx < NN) ? deg[idx] : 0;
        s += v[j];
    }
    sh[threadIdx.x] = s;
    __syncthreads();
    for (int off = 1; off < 256; off <<= 1) {
        int t = 0;
        if (threadIdx.x >= off) t = sh[threadIdx.x - off];
        __syncthreads();
        sh[threadIdx.x] += t;
        __syncthreads();
    }
    int run = sh[threadIdx.x] - s;
#pragma unroll
    for (int j = 0; j < 4; j++) {
        int idx = base + j;
        if (idx < NN) ptr[idx] = run;
        run += v[j];
    }
    if (threadIdx.x == 255) g_bsum[which][blk] = sh[255];
}

// ---------------- K5: build f0 table (pre-sync) + scan of block sums ----------------
__global__ void k_scan2p(const float* __restrict__ Wenc, const float* __restrict__ benc) {
    __shared__ int sh[256];
    int t = threadIdx.x;
    // pre-sync: table depends only on inputs
    for (int i = t; i < 9 * DD; i += 256) {
        int ty = i >> 6, d = i & 63;
        g_tab[i] = (float)(ty / 3) * Wenc[d] + (float)(ty % 3) * Wenc[64 + d] + benc[d];
    }
    cudaGridDependencySynchronize();
#pragma unroll
    for (int w = 0; w < 2; w++) {
        int v = (t < SCAN_NB) ? g_bsum[w][t] : 0;
        sh[t] = v;
        __syncthreads();
        for (int off = 1; off < 256; off <<= 1) {
            int x = 0;
            if (t >= off) x = sh[t - off];
            __syncthreads();
            sh[t] += x;
            __syncthreads();
        }
        if (t < SCAN_NB) g_bsum_s[w][t] = sh[t] - v;
        __syncthreads();
    }
    if (t == 0) { g_feptr[NN] = EE; g_beptr[NN] = EE; }
}

// ---------------- K6: add block offsets, init edge-scatter cursors ----------------
__global__ void k_scan3() {
    int stride = gridDim.x * blockDim.x;
    cudaGridDependencySynchronize();
    for (int i = blockIdx.x * blockDim.x + threadIdx.x; i < 2 * NN; i += stride) {
        if (i < NN) {
            int v = g_feptr[i] + g_bsum_s[0][i >> 10];
            g_feptr[i] = v;
            g_fcur_e[i] = v;
        } else {
            int j = i - NN;
            int v = g_beptr[j] + g_bsum_s[1][j >> 10];
            g_beptr[j] = v;
            g_bcur_e[j] = v;
        }
    }
}

// ---------------- K7: scatter edges into slot-ordered lists ----------------
__global__ void k_scatter_e(const int* __restrict__ ei, const int* __restrict__ fl) {
    int stride = gridDim.x * blockDim.x;
    cudaGridDependencySynchronize();
    for (int i = blockIdx.x * blockDim.x + threadIdx.x; i < EE; i += stride) {
        int src = ei[i], dst = ei[EE + i];
        int fp_src = g_fslot[src];             // packed slot | type<<20
        int fp_dst = g_fslot[dst];
        int p = atomicAdd(&g_fcur_e[fp_dst & SLOT_MASK], 1);
        g_fsrc[p] = fp_src;
        int bs_src = g_bslot[src];
        int bs_dst = g_bslot[dst];
        int q = atomicAdd(&g_bcur_e[bs_src], 1);
        int fidx = fp_dst | ((fl[dst] >= 1) ? FOUT_FLAG : 0);
        g_bedge[q] = make_int2(bs_dst, fidx);
    }
}

// ---------------- fused per-level forward: gather -> GEMM -> fout ----------------
__global__ void __launch_bounds__(256) k_flevel(int level,
                                                const float* __restrict__ W,
                                                const float* __restrict__ bias) {
    __shared__ float sW[64][64];
    __shared__ float sA[64][68];

    // pre-sync prologue: weights + bias are graph-constant inputs
    for (int i = threadIdx.x; i < 4096; i += 256) sW[i >> 6][i & 63] = W[i];
    int tx = threadIdx.x & 15, ty = threadIdx.x >> 4;
    int n0 = tx << 2, m0 = ty << 2;
    float4 bs = *(const float4*)(bias + n0);
    int r = threadIdx.x >> 2;
    int c16 = (threadIdx.x & 3) << 4;

    cudaGridDependencySynchronize();

    int start = g_foff[level];
    int cnt = g_foff[level + 1] - start;
    int foff1 = g_foff[1];
    int ntiles = (cnt + 63) >> 6;

    for (int tile = blockIdx.x; tile < ntiles; tile += gridDim.x) {
        int m = tile * 64 + r;
        float4 a0 = {0,0,0,0}, a1 = {0,0,0,0}, a2 = {0,0,0,0}, a3 = {0,0,0,0};
        if (m < cnt) {
            int slot = start + m;
            int e0 = __ldg(g_feptr + slot), e1 = __ldg(g_feptr + slot + 1);
            for (int e = e0; e < e1; e++) {
                int v = __ldg(g_fsrc + e);
                int s = v & SLOT_MASK;
                const float* hb = (s >= foff1 && s < start)
                    ? g_fout + (size_t)s * DD
                    : g_tab + ((v >> 20) & 0xF) * DD;
                const float4* b = (const float4*)(hb + c16);
                float4 v0 = b[0], v1 = b[1], v2 = b[2], v3 = b[3];
                a0.x += v0.x; a0.y += v0.y; a0.z += v0.z; a0.w += v0.w;
                a1.x += v1.x; a1.y += v1.y; a1.z += v1.z; a1.w += v1.w;
                a2.x += v2.x; a2.y += v2.y; a2.z += v2.z; a2.w += v2.w;
                a3.x += v3.x; a3.y += v3.y; a3.z += v3.z; a3.w += v3.w;
            }
        }
        *((float4*)&sA[r][c16 + 0]) = a0;
        *((float4*)&sA[r][c16 + 4]) = a1;
        *((float4*)&sA[r][c16 + 8]) = a2;
        *((float4*)&sA[r][c16 + 12]) = a3;
        __syncthreads();

        float c[4][4];
#pragma unroll
        for (int i = 0; i < 4; i++)
#pragma unroll
            for (int j = 0; j < 4; j++) c[i][j] = 0.f;

#pragma unroll 8
        for (int k = 0; k < 64; k++) {
            float4 b4 = *((const float4*)&sW[k][n0]);
            float x0 = sA[m0 + 0][k];
            float x1 = sA[m0 + 1][k];
            float x2 = sA[m0 + 2][k];
            float x3 = sA[m0 + 3][k];
            c[0][0] += x0 * b4.x; c[0][1] += x0 * b4.y; c[0][2] += x0 * b4.z; c[0][3] += x0 * b4.w;
            c[1][0] += x1 * b4.x; c[1][1] += x1 * b4.y; c[1][2] += x1 * b4.z; c[1][3] += x1 * b4.w;
            c[2][0] += x2 * b4.x; c[2][1] += x2 * b4.y; c[2][2] += x2 * b4.z; c[2][3] += x2 * b4.w;
            c[3][0] += x3 * b4.x; c[3][1] += x3 * b4.y; c[3][2] += x3 * b4.z; c[3][3] += x3 * b4.w;
        }

#pragma unroll
        for (int i = 0; i < 4; i++) {
            int mm = tile * 64 + m0 + i;
            if (mm < cnt) {
                int slot = start + mm;
                float dg = (float)__ldg(g_fdeg + slot);
                float4 o;
                o.x = c[i][0] + dg * bs.x;
                o.y = c[i][1] + dg * bs.y;
                o.z = c[i][2] + dg * bs.z;
                o.w = c[i][3] + dg * bs.w;
                *((float4*)(g_fout + (size_t)slot * DD + n0)) = o;
            }
        }
        __syncthreads();
    }
}

// ---------------- fused per-level backward: gather -> GEMM -> bout ----------------
__global__ void __launch_bounds__(256) k_blevel(int level,
                                                const float* __restrict__ W,
                                                const float* __restrict__ bias) {
    __shared__ float sW[64][64];
    __shared__ float sA[64][68];

    for (int i = threadIdx.x; i < 4096; i += 256) sW[i >> 6][i & 63] = W[i];
    int tx = threadIdx.x & 15, ty = threadIdx.x >> 4;
    int n0 = tx << 2, m0 = ty << 2;
    float4 bs = *(const float4*)(bias + n0);
    int r = threadIdx.x >> 2;
    int c16 = (threadIdx.x & 3) << 4;

    cudaGridDependencySynchronize();

    int start = g_boff[level];
    int cnt = g_boff[level + 1] - start;
    int boff1 = g_boff[1];
    int ntiles = (cnt + 63) >> 6;

    for (int tile = blockIdx.x; tile < ntiles; tile += gridDim.x) {
        int m = tile * 64 + r;
        float4 a0 = {0,0,0,0}, a1 = {0,0,0,0}, a2 = {0,0,0,0}, a3 = {0,0,0,0};
        if (m < cnt) {
            int slot = start + m;
            int e0 = __ldg(g_beptr + slot), e1 = __ldg(g_beptr + slot + 1);
            for (int e = e0; e < e1; e++) {
                int2 ee = __ldg(g_bedge + e);
                int s = ee.x;
                const float* hb;
                if (s >= boff1 && s < start) {
                    hb = g_bout + (size_t)s * DD;
                } else {
                    int f = ee.y;
                    hb = (f & FOUT_FLAG)
                        ? g_fout + (size_t)(f & SLOT_MASK) * DD
                        : g_tab + ((f >> 20) & 0xF) * DD;
                }
                const float4* b = (const float4*)(hb + c16);
                float4 v0 = b[0], v1 = b[1], v2 = b[2], v3 = b[3];
                a0.x += v0.x; a0.y += v0.y; a0.z += v0.z; a0.w += v0.w;
                a1.x += v1.x; a1.y += v1.y; a1.z += v1.z; a1.w += v1.w;
                a2.x += v2.x; a2.y += v2.y; a2.z += v2.z; a2.w += v2.w;
                a3.x += v3.x; a3.y += v3.y; a3.z += v3.z; a3.w += v3.w;
            }
        }
        *((float4*)&sA[r][c16 + 0]) = a0;
        *((float4*)&sA[r][c16 + 4]) = a1;
        *((float4*)&sA[r][c16 + 8]) = a2;
        *((float4*)&sA[r][c16 + 12]) = a3;
        __syncthreads();

        float c[4][4];
#pragma unroll
        for (int i = 0; i < 4; i++)
#pragma unroll
            for (int j = 0; j < 4; j++) c[i][j] = 0.f;

#pragma unroll 8
        for (int k = 0; k < 64; k++) {
            float4 b4 = *((const float4*)&sW[k][n0]);
            float x0 = sA[m0 + 0][k];
            float x1 = sA[m0 + 1][k];
            float x2 = sA[m0 + 2][k];
            float x3 = sA[m0 + 3][k];
            c[0][0] += x0 * b4.x; c[0][1] += x0 * b4.y; c[0][2] += x0 * b4.z; c[0][3] += x0 * b4.w;
            c[1][0] += x1 * b4.x; c[1][1] += x1 * b4.y; c[1][2] += x1 * b4.z; c[1][3] += x1 * b4.w;
            c[2][0] += x2 * b4.x; c[2][1] += x2 * b4.y; c[2][2] += x2 * b4.z; c[2][3] += x2 * b4.w;
            c[3][0] += x3 * b4.x; c[3][1] += x3 * b4.y; c[3][2] += x3 * b4.z; c[3][3] += x3 * b4.w;
        }

#pragma unroll
        for (int i = 0; i < 4; i++) {
            int mm = tile * 64 + m0 + i;
            if (mm < cnt) {
                int slot = start + mm;
                float dg = (float)__ldg(g_bdeg + slot);
                float4 o;
                o.x = c[i][0] + dg * bs.x;
                o.y = c[i][1] + dg * bs.y;
                o.z = c[i][2] + dg * bs.z;
                o.w = c[i][3] + dg * bs.w;
                *((float4*)(g_bout + (size_t)slot * DD + n0)) = o;
            }
        }
        __syncthreads();
    }
}

// ---------------- readout ----------------
__device__ __forceinline__ void pool_flush(int cb, float2 mx, float2 sm, int lane,
                                           float* out) {
    int d = 2 * lane;
    unsigned* uo = (unsigned*)out;
    atomicMax(&uo[cb * 128 + d], enc_f(mx.x));
    atomicMax(&uo[cb * 128 + d + 1], enc_f(mx.y));
    atomicAdd(&out[cb * 128 + 64 + d], sm.x);
    atomicAdd(&out[cb * 128 + 64 + d + 1], sm.y);
}

__global__ void k_pool(const int* __restrict__ nt, const int* __restrict__ batch,
                       const int* __restrict__ fl, const int* __restrict__ bl,
                       float* __restrict__ out) {
    int chunk = (NN + gridDim.x - 1) / gridDim.x;
    int s = blockIdx.x * chunk;
    int e = min(NN, s + chunk);
    int warp = threadIdx.x >> 5, lane = threadIdx.x & 31;
    int nw = blockDim.x >> 5;
    cudaGridDependencySynchronize();
    if (s >= e) return;
    int len = e - s;
    int wchunk = (len + nw - 1) / nw;
    int ws = s + warp * wchunk;
    int we = min(e, ws + wchunk);
    float2 mx = make_float2(NEGMAX, NEGMAX);
    float2 sm = make_float2(0.f, 0.f);
    int cb = (ws < we) ? batch[ws] : -1;
    for (int n = ws; n < we; n++) {
        int bb = batch[n];
        if (bb != cb) {
            pool_flush(cb, mx, sm, lane, out);
            mx = make_float2(NEGMAX, NEGMAX);
            sm = make_float2(0.f, 0.f);
            cb = bb;
        }
        if (nt[n] == 1) {
            const float* base;
            if (bl[n] >= 1) {
                base = g_bout + (size_t)g_bslot[n] * DD;
            } else {
                int fp = g_fslot[n];
                base = (fl[n] >= 1)
                    ? g_fout + (size_t)(fp & SLOT_MASK) * DD
                    : g_tab + ((fp >> 20) & 0xF) * DD;
            }
            float2 v = *((const float2*)base + lane);
            mx.x = fmaxf(mx.x, v.x);
            mx.y = fmaxf(mx.y, v.y);
            sm.x += v.x;
            sm.y += v.y;
        }
    }
    if (cb >= 0) pool_flush(cb, mx, sm, lane, out);
}

__global__ void k_fixup(float* __restrict__ out) {
    cudaGridDependencySynchronize();
    int i = threadIdx.x;           // 1024 = B*64
    int b = i >> 6, d = i & 63;
    int pos = b * 128 + d;
    unsigned u = ((unsigned*)out)[pos];
    out[pos] = dec_f(u);
}

// ---------------- PDL launch helper ----------------
template <typename... Args>
static void pdl(void (*kern)(Args...), int grid, int block, Args... args) {
    cudaLaunchConfig_t cfg = {};
    cfg.gridDim = dim3(grid, 1, 1);
    cfg.blockDim = dim3(block, 1, 1);
    cfg.stream = 0;
    cudaLaunchAttribute attr;
    attr.id = cudaLaunchAttributeProgrammaticStreamSerialization;
    attr.val.programmaticStreamSerializationAllowed = 1;
    cfg.attrs = &attr;
    cfg.numAttrs = 1;
    cudaLaunchKernelEx(&cfg, kern, args...);
}

// ---------------- launch ----------------
extern "C" void kernel_launch(void* const* d_in, const int* in_sizes, int n_in,
                              void* d_out, int out_size) {
    const int* nt    = (const int*)d_in[0];
    const int* nip   = (const int*)d_in[1];
    const int* ei    = (const int*)d_in[2];
    const int* fl    = (const int*)d_in[3];
    const int* bl    = (const int*)d_in[4];
    const int* batch = (const int*)d_in[5];
    const float* W_enc = (const float*)d_in[6];
    const float* b_enc = (const float*)d_in[7];
    const float* W_f   = (const float*)d_in[8];
    const float* b_f   = (const float*)d_in[9];
    const float* W_b   = (const float*)d_in[10];
    const float* b_b   = (const float*)d_in[11];
    float* out = (float*)d_out;

    k_zero<<<196, 256>>>(out);
    pdl(k_deg_hist, NB2, 256, ei, fl, bl);
    pdl(k_hscan, 1, 768);
    pdl(k_assign2, NB2, 256, fl, bl, nt, nip);
    pdl(k_scan1, 2 * SCAN_NB, 256);
    pdl(k_scan2p, 1, 256, W_enc, b_enc);
    pdl(k_scan3, 784, 256);
    pdl(k_scatter_e, 1600, 256, ei, fl);

    for (int l = 1; l < NLVL; l++) pdl(k_flevel, 320, 256, l, W_f, b_f);
    for (int l = 1; l < NLVL; l++) pdl(k_blevel, 320, 256, l, W_b, b_b);

    pdl(k_pool, 592, 256, nt, batch, fl, bl, out);
    pdl(k_fixup, 1, 1024, out);
}

// round 12
// speedup vs baseline: 1.9975x; 1.0457x over previous
#include <cuda_runtime.h>

#define NN 200000
#define EE 400000
#define DD 64
#define BBATCH 16
#define NLVL 12
#define SCAN_NB ((NN + 1023) / 1024)   // 196 (degree scans, 1024/block)
#define NB2 784                        // node-chunk blocks (256 nodes/block)
#define PGRID 296
#define SLOT_MASK 0xFFFFF
#define FOUT_FLAG 0x40000000

// ---------------- device scratch ----------------
__device__ float g_fout[NN * DD];       // slot-indexed forward outputs
__device__ float g_bout[NN * DD];       // slot-indexed backward outputs
__device__ float g_tab[9 * DD];         // 9 distinct f0 rows (nt*3+nip)
__device__ int g_indeg[NN], g_outdeg[NN];
__device__ int g_fslot[NN], g_bslot[NN];     // node -> slot (fslot packs type<<20)
__device__ int g_fdeg[NN], g_bdeg[NN];       // slot-indexed degree
__device__ int g_feptr[NN + 1], g_beptr[NN + 1];
__device__ int g_fcur_e[NN], g_bcur_e[NN];
__device__ int g_fsrc[EE];              // fwd edges by dst-slot: packed fslot[src]
__device__ int2 g_bedge[EE];            // bwd edges by src-slot: (bslot[dst], fidx[dst])
__device__ int g_foff[NLVL + 1], g_boff[NLVL + 1];
__device__ int g_lhist[2 * NLVL * NB2];
__device__ int g_bsum[2][SCAN_NB], g_bsum_s[2][SCAN_NB];
// grid barrier (generation counter survives graph replays)
__device__ unsigned g_cnt = 0;
__device__ volatile unsigned g_gen = 0;

__device__ __forceinline__ unsigned enc_f(float f) {
    unsigned u = __float_as_uint(f);
    return (u & 0x80000000u) ? ~u : (u | 0x80000000u);
}
__device__ __forceinline__ float dec_f(unsigned u) {
    return (u & 0x80000000u) ? __uint_as_float(u & 0x7FFFFFFFu)
                             : __uint_as_float(~u);
}
#define NEGMAX (-3.402823466e38f)

// ---------------- K0: zero degree arrays + init output buffer ----------------
__global__ void k_zero(float* __restrict__ out) {
    int stride = gridDim.x * blockDim.x;
    for (int i = blockIdx.x * blockDim.x + threadIdx.x; i < NN; i += stride) {
        g_indeg[i] = 0;
        g_outdeg[i] = 0;
        if (i < BBATCH * 2 * DD) {
            int col = i & 127;
            ((unsigned*)out)[i] = (col < 64) ? 0x00800000u : 0u;
        }
    }
}

// ---------------- K1: node level hists (pre-sync) + edge degrees (post-sync) ----------------
__global__ void k_deg_hist(const int* __restrict__ ei, const int* __restrict__ fl,
                           const int* __restrict__ bl) {
    __shared__ int sh[2 * NLVL];
    int t = threadIdx.x;
    if (t < 2 * NLVL) sh[t] = 0;
    __syncthreads();
    int idx = blockIdx.x * 256 + t;          // one node per thread
    if (idx < NN) {
        atomicAdd(&sh[fl[idx]], 1);
        atomicAdd(&sh[NLVL + bl[idx]], 1);
    }
    cudaGridDependencySynchronize();         // wait k_zero (g_indeg/outdeg ready)
    int stride = gridDim.x * blockDim.x;
    for (int i = blockIdx.x * blockDim.x + t; i < EE; i += stride) {
        atomicAdd(&g_indeg[ei[EE + i]], 1);
        atomicAdd(&g_outdeg[ei[i]], 1);
    }
    __syncthreads();
    if (t < 2 * NLVL) g_lhist[t * NB2 + blockIdx.x] = sh[t];
}

// ---------------- K2: scan block hists -> per-(blk,lvl) offsets + foff/boff ----------------
__global__ void k_hscan() {
    __shared__ int tot[2 * NLVL];
    __shared__ int off_s[2][NLVL + 1];
    int t = threadIdx.x;
    int wid = t >> 5, lane = t & 31;       // 24 warps
    cudaGridDependencySynchronize();
    int* row = g_lhist + wid * NB2;
    int carry = 0;
#pragma unroll
    for (int r = 0; r < (NB2 + 31) / 32; r++) {
        int idx = r * 32 + lane;
        int v = (idx < NB2) ? row[idx] : 0;
        int incl = v;
#pragma unroll
        for (int o = 1; o < 32; o <<= 1) {
            int n = __shfl_up_sync(0xffffffffu, incl, o);
            if (lane >= o) incl += n;
        }
        if (idx < NB2) row[idx] = incl - v + carry;
        carry += __shfl_sync(0xffffffffu, incl, 31);
    }
    if (lane == 0) tot[wid] = carry;
    __syncthreads();
    if (wid < 2) {
        int hv = (lane < NLVL) ? tot[wid * NLVL + lane] : 0;
        int v = hv;
#pragma unroll
        for (int o = 1; o < 32; o <<= 1) {
            int n = __shfl_up_sync(0xffffffffu, v, o);
            if (lane >= o) v += n;
        }
        int excl = v - hv;
        if (lane <= NLVL) {
            off_s[wid][lane] = excl;
            (wid ? g_boff : g_foff)[lane] = excl;
        }
    }
    __syncthreads();
    int add = off_s[wid / NLVL][wid % NLVL];
#pragma unroll
    for (int r = 0; r < (NB2 + 31) / 32; r++) {
        int idx = r * 32 + lane;
        if (idx < NB2) row[idx] += add;
    }
}

// ---------------- K3: assign slots (pack nt/nip type into fslot) ----------------
__global__ void k_assign2(const int* __restrict__ fl, const int* __restrict__ bl,
                          const int* __restrict__ nt, const int* __restrict__ nip) {
    __shared__ int sc[2 * NLVL];
    int t = threadIdx.x;
    int v = blockIdx.x * 256 + t;            // one node per thread
    int type = 0, flv = 0, blv = 0;
    if (v < NN) {
        type = nt[v] * 3 + nip[v];
        flv = fl[v];
        blv = bl[v];
    }
    cudaGridDependencySynchronize();
    if (t < 2 * NLVL) sc[t] = g_lhist[t * NB2 + blockIdx.x];
    __syncthreads();
    if (v < NN) {
        int s = atomicAdd(&sc[flv], 1);
        g_fslot[v] = s | (type << 20);
        g_fdeg[s] = g_indeg[v];
        int s2 = atomicAdd(&sc[NLVL + blv], 1);
        g_bslot[v] = s2;
        g_bdeg[s2] = g_outdeg[v];
    }
}

// ---------------- K4: block-local exclusive scans of slot degrees ----------------
__global__ void k_scan1() {
    int which = blockIdx.x / SCAN_NB;   // 0 = fdeg, 1 = bdeg
    int blk = blockIdx.x % SCAN_NB;
    const int* deg = which ? g_bdeg : g_fdeg;
    int* ptr = which ? g_beptr : g_feptr;
    __shared__ int sh[256];
    int base = blk * 1024 + threadIdx.x * 4;
    cudaGridDependencySynchronize();
    int v[4];
    int s = 0;
#pragma unroll
    for (int j = 0; j < 4; j++) {
        int idx = base + j;
        v[j] = (idx < NN) ? deg[idx] : 0;
        s += v[j];
    }
    sh[threadIdx.x] = s;
    __syncthreads();
    for (int off = 1; off < 256; off <<= 1) {
        int t = 0;
        if (threadIdx.x >= off) t = sh[threadIdx.x - off];
        __syncthreads();
        sh[threadIdx.x] += t;
        __syncthreads();
    }
    int run = sh[threadIdx.x] - s;
#pragma unroll
    for (int j = 0; j < 4; j++) {
        int idx = base + j;
        if (idx < NN) ptr[idx] = run;
        run += v[j];
    }
    if (threadIdx.x == 255) g_bsum[which][blk] = sh[255];
}

// ---------------- K5: build f0 table (pre-sync) + scan of block sums ----------------
__global__ void k_scan2p(const float* __restrict__ Wenc, const float* __restrict__ benc) {
    __shared__ int sh[256];
    int t = threadIdx.x;
    for (int i = t; i < 9 * DD; i += 256) {
        int ty = i >> 6, d = i & 63;
        g_tab[i] = (float)(ty / 3) * Wenc[d] + (float)(ty % 3) * Wenc[64 + d] + benc[d];
    }
    cudaGridDependencySynchronize();
#pragma unroll
    for (int w = 0; w < 2; w++) {
        int v = (t < SCAN_NB) ? g_bsum[w][t] : 0;
        sh[t] = v;
        __syncthreads();
        for (int off = 1; off < 256; off <<= 1) {
            int x = 0;
            if (t >= off) x = sh[t - off];
            __syncthreads();
            sh[t] += x;
            __syncthreads();
        }
        if (t < SCAN_NB) g_bsum_s[w][t] = sh[t] - v;
        __syncthreads();
    }
    if (t == 0) { g_feptr[NN] = EE; g_beptr[NN] = EE; }
}

// ---------------- K6: add block offsets, init edge-scatter cursors ----------------
__global__ void k_scan3() {
    int stride = gridDim.x * blockDim.x;
    cudaGridDependencySynchronize();
    for (int i = blockIdx.x * blockDim.x + threadIdx.x; i < 2 * NN; i += stride) {
        if (i < NN) {
            int v = g_feptr[i] + g_bsum_s[0][i >> 10];
            g_feptr[i] = v;
            g_fcur_e[i] = v;
        } else {
            int j = i - NN;
            int v = g_beptr[j] + g_bsum_s[1][j >> 10];
            g_beptr[j] = v;
            g_bcur_e[j] = v;
        }
    }
}

// ---------------- K7: scatter edges into slot-ordered lists ----------------
__global__ void k_scatter_e(const int* __restrict__ ei, const int* __restrict__ fl) {
    int stride = gridDim.x * blockDim.x;
    cudaGridDependencySynchronize();
    for (int i = blockIdx.x * blockDim.x + threadIdx.x; i < EE; i += stride) {
        int src = ei[i], dst = ei[EE + i];
        int fp_src = g_fslot[src];             // packed slot | type<<20
        int fp_dst = g_fslot[dst];
        int p = atomicAdd(&g_fcur_e[fp_dst & SLOT_MASK], 1);
        g_fsrc[p] = fp_src;
        int bs_src = g_bslot[src];
        int bs_dst = g_bslot[dst];
        int q = atomicAdd(&g_bcur_e[bs_src], 1);
        int fidx = fp_dst | ((fl[dst] >= 1) ? FOUT_FLAG : 0);
        g_bedge[q] = make_int2(bs_dst, fidx);
    }
}

// ---------------- grid-wide software barrier ----------------
__device__ __forceinline__ void grid_bar(unsigned target) {
    __threadfence();
    __syncthreads();
    if (threadIdx.x == 0) {
        unsigned t = atomicAdd(&g_cnt, 1u);
        if (t == (unsigned)gridDim.x - 1u) {
            g_cnt = 0u;
            __threadfence();
            g_gen = target;
        } else {
            while (g_gen != target) __nanosleep(64);
        }
        __threadfence();
    }
    __syncthreads();
}

__device__ __forceinline__ void pool_flush(int cb, float2 mx, float2 sm, int lane,
                                           float* out) {
    int d = 2 * lane;
    unsigned* uo = (unsigned*)out;
    atomicMax(&uo[cb * 128 + d], enc_f(mx.x));
    atomicMax(&uo[cb * 128 + d + 1], enc_f(mx.y));
    atomicAdd(&out[cb * 128 + 64 + d], sm.x);
    atomicAdd(&out[cb * 128 + 64 + d + 1], sm.y);
}

// ---------------- persistent: 22 fused levels + pool + fixup ----------------
__global__ void __launch_bounds__(256, 2) k_persist(
    const int* __restrict__ nt, const int* __restrict__ batch,
    const int* __restrict__ fl, const int* __restrict__ bl,
    const float* __restrict__ W_f, const float* __restrict__ b_f,
    const float* __restrict__ W_b, const float* __restrict__ b_b,
    float* __restrict__ out) {

    __shared__ float sW[64][64];
    __shared__ float sA[64][68];

    const int lane = threadIdx.x & 31;
    const int tx = threadIdx.x & 15, ty = threadIdx.x >> 4;
    const int n0 = tx << 2, m0 = ty << 2;
    const int r = threadIdx.x >> 2;
    const int c16 = (threadIdx.x & 3) << 4;

    // pre-sync prologue: dir-0 weights are graph-constant inputs
    for (int i = threadIdx.x; i < 4096; i += 256) sW[i >> 6][i & 63] = W_f[i];

    cudaGridDependencySynchronize();

    unsigned base = 0, nbar = 0;
    if (threadIdx.x == 0) base = g_gen;

    for (int dir = 0; dir < 2; dir++) {
        const float* bias = dir ? b_b : b_f;
        const int* off = dir ? g_boff : g_foff;
        const int* eptr = dir ? g_beptr : g_feptr;
        const int* deg = dir ? g_bdeg : g_fdeg;

        if (dir == 1) {
            // sW free to overwrite: last read preceded the prior grid_bar's syncthreads
            for (int i = threadIdx.x; i < 4096; i += 256) sW[i >> 6][i & 63] = W_b[i];
        }
        float4 bs = *(const float4*)(bias + n0);
        int off1 = off[1];

        for (int l = 1; l < NLVL; l++) {
            int start = off[l];
            int cnt = off[l + 1] - start;
            int ntiles = (cnt + 63) >> 6;

            for (int tile = blockIdx.x; tile < ntiles; tile += gridDim.x) {
                int m = tile * 64 + r;
                float4 a0 = {0,0,0,0}, a1 = {0,0,0,0}, a2 = {0,0,0,0}, a3 = {0,0,0,0};
                if (m < cnt) {
                    int slot = start + m;
                    int e0 = __ldg(eptr + slot), e1 = __ldg(eptr + slot + 1);
                    if (dir == 0) {
                        for (int e = e0; e < e1; e++) {
                            int v = __ldg(g_fsrc + e);
                            int s = v & SLOT_MASK;
                            const float* hb = (s >= off1 && s < start)
                                ? g_fout + (size_t)s * DD
                                : g_tab + ((v >> 20) & 0xF) * DD;
                            const float4* b = (const float4*)(hb + c16);
                            float4 v0 = b[0], v1 = b[1], v2 = b[2], v3 = b[3];
                            a0.x += v0.x; a0.y += v0.y; a0.z += v0.z; a0.w += v0.w;
                            a1.x += v1.x; a1.y += v1.y; a1.z += v1.z; a1.w += v1.w;
                            a2.x += v2.x; a2.y += v2.y; a2.z += v2.z; a2.w += v2.w;
                            a3.x += v3.x; a3.y += v3.y; a3.z += v3.z; a3.w += v3.w;
                        }
                    } else {
                        for (int e = e0; e < e1; e++) {
                            int2 ee = __ldg(g_bedge + e);
                            int s = ee.x;
                            const float* hb;
                            if (s >= off1 && s < start) {
                                hb = g_bout + (size_t)s * DD;
                            } else {
                                int f = ee.y;
                                hb = (f & FOUT_FLAG)
                                    ? g_fout + (size_t)(f & SLOT_MASK) * DD
                                    : g_tab + ((f >> 20) & 0xF) * DD;
                            }
                            const float4* b = (const float4*)(hb + c16);
                            float4 v0 = b[0], v1 = b[1], v2 = b[2], v3 = b[3];
                            a0.x += v0.x; a0.y += v0.y; a0.z += v0.z; a0.w += v0.w;
                            a1.x += v1.x; a1.y += v1.y; a1.z += v1.z; a1.w += v1.w;
                            a2.x += v2.x; a2.y += v2.y; a2.z += v2.z; a2.w += v2.w;
                            a3.x += v3.x; a3.y += v3.y; a3.z += v3.z; a3.w += v3.w;
                        }
                    }
                }
                *((float4*)&sA[r][c16 + 0]) = a0;
                *((float4*)&sA[r][c16 + 4]) = a1;
                *((float4*)&sA[r][c16 + 8]) = a2;
                *((float4*)&sA[r][c16 + 12]) = a3;
                __syncthreads();

                float c[4][4];
#pragma unroll
                for (int i = 0; i < 4; i++)
#pragma unroll
                    for (int j = 0; j < 4; j++) c[i][j] = 0.f;

#pragma unroll 8
                for (int k = 0; k < 64; k++) {
                    float4 b4 = *((const float4*)&sW[k][n0]);
                    float x0 = sA[m0 + 0][k];
                    float x1 = sA[m0 + 1][k];
                    float x2 = sA[m0 + 2][k];
                    float x3 = sA[m0 + 3][k];
                    c[0][0] += x0 * b4.x; c[0][1] += x0 * b4.y; c[0][2] += x0 * b4.z; c[0][3] += x0 * b4.w;
                    c[1][0] += x1 * b4.x; c[1][1] += x1 * b4.y; c[1][2] += x1 * b4.z; c[1][3] += x1 * b4.w;
                    c[2][0] += x2 * b4.x; c[2][1] += x2 * b4.y; c[2][2] += x2 * b4.z; c[2][3] += x2 * b4.w;
                    c[3][0] += x3 * b4.x; c[3][1] += x3 * b4.y; c[3][2] += x3 * b4.z; c[3][3] += x3 * b4.w;
                }

                float* outbuf = dir ? g_bout : g_fout;
#pragma unroll
                for (int i = 0; i < 4; i++) {
                    int mm = tile * 64 + m0 + i;
                    if (mm < cnt) {
                        int slot = start + mm;
                        float dg = (float)__ldg(deg + slot);
                        float4 o;
                        o.x = c[i][0] + dg * bs.x;
                        o.y = c[i][1] + dg * bs.y;
                        o.z = c[i][2] + dg * bs.z;
                        o.w = c[i][3] + dg * bs.w;
                        *((float4*)(outbuf + (size_t)slot * DD + n0)) = o;
                    }
                }
                __syncthreads();
            }
            grid_bar(base + (++nbar));
        }
    }

    // ---- pool phase ----
    {
        int chunk = (NN + gridDim.x - 1) / gridDim.x;
        int s = blockIdx.x * chunk;
        int e = min(NN, s + chunk);
        if (s < e) {
            int warp = threadIdx.x >> 5;
            int nw = 256 >> 5;
            int len = e - s;
            int wchunk = (len + nw - 1) / nw;
            int ws = s + warp * wchunk;
            int we = min(e, ws + wchunk);
            float2 mx = make_float2(NEGMAX, NEGMAX);
            float2 sm = make_float2(0.f, 0.f);
            int cb = (ws < we) ? batch[ws] : -1;
            for (int n = ws; n < we; n++) {
                int bb = batch[n];
                if (bb != cb) {
                    pool_flush(cb, mx, sm, lane, out);
                    mx = make_float2(NEGMAX, NEGMAX);
                    sm = make_float2(0.f, 0.f);
                    cb = bb;
                }
                if (nt[n] == 1) {
                    const float* basep;
                    if (bl[n] >= 1) {
                        basep = g_bout + (size_t)g_bslot[n] * DD;
                    } else {
                        int fp = g_fslot[n];
                        basep = (fl[n] >= 1)
                            ? g_fout + (size_t)(fp & SLOT_MASK) * DD
                            : g_tab + ((fp >> 20) & 0xF) * DD;
                    }
                    float2 v = *((const float2*)basep + lane);
                    mx.x = fmaxf(mx.x, v.x);
                    mx.y = fmaxf(mx.y, v.y);
                    sm.x += v.x;
                    sm.y += v.y;
                }
            }
            if (cb >= 0) pool_flush(cb, mx, sm, lane, out);
        }
    }
    grid_bar(base + (++nbar));

    // ---- fixup (block 0) ----
    if (blockIdx.x == 0) {
        for (int i = threadIdx.x; i < BBATCH * DD; i += 256) {
            int b = i >> 6, d = i & 63;
            int pos = b * 128 + d;
            unsigned u = __ldcg((const unsigned*)out + pos);
            out[pos] = dec_f(u);
        }
    }
}

// ---------------- PDL launch helper ----------------
template <typename... Args>
static void pdl(void (*kern)(Args...), int grid, int block, Args... args) {
    cudaLaunchConfig_t cfg = {};
    cfg.gridDim = dim3(grid, 1, 1);
    cfg.blockDim = dim3(block, 1, 1);
    cfg.stream = 0;
    cudaLaunchAttribute attr;
    attr.id = cudaLaunchAttributeProgrammaticStreamSerialization;
    attr.val.programmaticStreamSerializationAllowed = 1;
    cfg.attrs = &attr;
    cfg.numAttrs = 1;
    cudaLaunchKernelEx(&cfg, kern, args...);
}

// ---------------- launch ----------------
extern "C" void kernel_launch(void* const* d_in, const int* in_sizes, int n_in,
                              void* d_out, int out_size) {
    const int* nt    = (const int*)d_in[0];
    const int* nip   = (const int*)d_in[1];
    const int* ei    = (const int*)d_in[2];
    const int* fl    = (const int*)d_in[3];
    const int* bl    = (const int*)d_in[4];
    const int* batch = (const int*)d_in[5];
    const float* W_enc = (const float*)d_in[6];
    const float* b_enc = (const float*)d_in[7];
    const float* W_f   = (const float*)d_in[8];
    const float* b_f   = (const float*)d_in[9];
    const float* W_b   = (const float*)d_in[10];
    const float* b_b   = (const float*)d_in[11];
    float* out = (float*)d_out;

    k_zero<<<196, 256>>>(out);
    pdl(k_deg_hist, NB2, 256, ei, fl, bl);
    pdl(k_hscan, 1, 768);
    pdl(k_assign2, NB2, 256, fl, bl, nt, nip);
    pdl(k_scan1, 2 * SCAN_NB, 256);
    pdl(k_scan2p, 1, 256, W_enc, b_enc);
    pdl(k_scan3, 784, 256);
    pdl(k_scatter_e, 1600, 256, ei, fl);
    pdl(k_persist, PGRID, 256, nt, batch, fl, bl, W_f, b_f, W_b, b_b, out);
}